// round 1
// baseline (speedup 1.0000x reference)
#include <cuda_runtime.h>

#define Nn   16
#define Cc   256
#define HWn  4608
#define Sn   64
#define SPLIT 24
#define KCH  (HWn / SPLIT)   // 192

// ---------------- scratch (device globals; no allocs allowed) ----------------
__device__ __align__(16) float g_xs [Nn * Sn * HWn];          // 18.9 MB
__device__ __align__(16) float g_t  [Nn * Sn * HWn];          // pre-softmax t, then comb (in place)
__device__ __align__(16) float g_xnp[Nn * SPLIT * Sn * Sn];   // split-K partials of xn
__device__ __align__(16) float g_h2 [Nn * Sn * Sn];
__device__ __align__(16) float g_M  [Nn * Cc * Sn];           // We @ hh
__device__ __align__(16) float g_ext[Nn * Cc * HWn];          // 75.5 MB
__device__ float g_mean[Cc];
__device__ float g_istd[Cc];

// ---------------- k1: fused xs / t GEMM  (128x4608x256 per batch) ----------------
// rows 0..63 -> xs = Ws@x + bs ; rows 64..127 -> t = (Wp@x + bp) * (1 + sigmoid(e1-e0))
__global__ void __launch_bounds__(256) k1_proj(
    const float* __restrict__ x, const float* __restrict__ edge,
    const float* __restrict__ Ws, const float* __restrict__ bs,
    const float* __restrict__ Wp, const float* __restrict__ bp)
{
    __shared__ float sW[128][33];   // K-chunk 32, padded (conflict-free)
    __shared__ float sX[32][128];
    int n  = blockIdx.y;
    int k0 = blockIdx.x * 128;
    int tid = threadIdx.x;
    int tx = tid & 15, ty = tid >> 4;
    float acc[8][8] = {};
    const float* xb = x + n * Cc * HWn;

    for (int c0 = 0; c0 < Cc; c0 += 32) {
        #pragma unroll
        for (int t = 0; t < 16; t++) {
            int idx = tid + t * 256;        // 128*32
            int r = idx >> 5, c = idx & 31;
            const float* src = (r < 64) ? (Ws + r * 256) : (Wp + (r - 64) * 256);
            sW[r][c] = src[c0 + c];
        }
        #pragma unroll
        for (int t = 0; t < 16; t++) {
            int idx = tid + t * 256;        // 32*128
            int cc = idx >> 7, k = idx & 127;
            sX[cc][k] = xb[(c0 + cc) * HWn + k0 + k];
        }
        __syncthreads();
        #pragma unroll
        for (int cc = 0; cc < 32; cc++) {
            float4 b0 = *(const float4*)&sX[cc][tx * 8];
            float4 b1 = *(const float4*)&sX[cc][tx * 8 + 4];
            #pragma unroll
            for (int i = 0; i < 8; i++) {
                float w = sW[ty * 8 + i][cc];
                acc[i][0] += w * b0.x; acc[i][1] += w * b0.y;
                acc[i][2] += w * b0.z; acc[i][3] += w * b0.w;
                acc[i][4] += w * b1.x; acc[i][5] += w * b1.y;
                acc[i][6] += w * b1.z; acc[i][7] += w * b1.w;
            }
        }
        __syncthreads();
    }

    int kbase = k0 + tx * 8;
    if (ty < 8) {
        #pragma unroll
        for (int i = 0; i < 8; i++) {
            int s = ty * 8 + i;
            float bv = bs[s];
            float* dst = g_xs + (n * Sn + s) * HWn + kbase;
            float4 v0 = {acc[i][0] + bv, acc[i][1] + bv, acc[i][2] + bv, acc[i][3] + bv};
            float4 v1 = {acc[i][4] + bv, acc[i][5] + bv, acc[i][6] + bv, acc[i][7] + bv};
            *(float4*)dst = v0; *(float4*)(dst + 4) = v1;
        }
    } else {
        float gate[8];
        #pragma unroll
        for (int j = 0; j < 8; j++) {
            int k = kbase + j;
            float e0 = edge[(n * 2 + 0) * HWn + k];
            float e1 = edge[(n * 2 + 1) * HWn + k];
            // 1 + sigmoid(e1-e0) = 2 - 1/(1+exp(e1-e0))
            gate[j] = 2.0f - 1.0f / (1.0f + __expf(e1 - e0));
        }
        #pragma unroll
        for (int i = 0; i < 8; i++) {
            int s = (ty - 8) * 8 + i;
            float bv = bp[s];
            float* dst = g_t + (n * Sn + s) * HWn + kbase;
            float4 v0 = {(acc[i][0] + bv) * gate[0], (acc[i][1] + bv) * gate[1],
                         (acc[i][2] + bv) * gate[2], (acc[i][3] + bv) * gate[3]};
            float4 v1 = {(acc[i][4] + bv) * gate[4], (acc[i][5] + bv) * gate[5],
                         (acc[i][6] + bv) * gate[6], (acc[i][7] + bv) * gate[7]};
            *(float4*)dst = v0; *(float4*)(dst + 4) = v1;
        }
    }
}

// ---------------- k2: row softmax over HW (1024 rows, in place on g_t) ----------------
__global__ void __launch_bounds__(256) k2_softmax()
{
    int row = blockIdx.x;
    float* p = g_t + row * HWn;
    int tid = threadIdx.x;
    __shared__ float red[256];
    float v[18];
    float m = -1e30f;
    #pragma unroll
    for (int t = 0; t < 18; t++) { v[t] = p[tid + t * 256]; m = fmaxf(m, v[t]); }
    red[tid] = m; __syncthreads();
    #pragma unroll
    for (int s = 128; s > 0; s >>= 1) {
        if (tid < s) red[tid] = fmaxf(red[tid], red[tid + s]);
        __syncthreads();
    }
    m = red[0];
    __syncthreads();
    float sum = 0.0f;
    #pragma unroll
    for (int t = 0; t < 18; t++) { v[t] = __expf(v[t] - m); sum += v[t]; }
    red[tid] = sum; __syncthreads();
    #pragma unroll
    for (int s = 128; s > 0; s >>= 1) {
        if (tid < s) red[tid] += red[tid + s];
        __syncthreads();
    }
    float inv = 1.0f / red[0];
    #pragma unroll
    for (int t = 0; t < 18; t++) p[tid + t * 256] = v[t] * inv;
}

// ---------------- k3: xn[s,t] = sum_k xs[s,k]*comb[t,k]  (split-K partials) ----------------
__global__ void __launch_bounds__(256) k3_xn()
{
    int sp = blockIdx.x, n = blockIdx.y;
    int koff = sp * KCH;
    __shared__ float sA[64][33], sB[64][33];
    int tid = threadIdx.x, tx = tid & 15, ty = tid >> 4;
    float acc[4][4] = {};
    const float* A = g_xs + n * Sn * HWn;
    const float* B = g_t  + n * Sn * HWn;

    for (int kc = 0; kc < KCH; kc += 32) {
        #pragma unroll
        for (int t = 0; t < 8; t++) {
            int idx = tid + t * 256;        // 64*32
            int r = idx >> 5, k = idx & 31;
            sA[r][k] = A[r * HWn + koff + kc + k];
            sB[r][k] = B[r * HWn + koff + kc + k];
        }
        __syncthreads();
        #pragma unroll
        for (int k = 0; k < 32; k++) {
            float a0 = sA[ty * 4 + 0][k], a1 = sA[ty * 4 + 1][k];
            float a2 = sA[ty * 4 + 2][k], a3 = sA[ty * 4 + 3][k];
            float b0 = sB[tx * 4 + 0][k], b1 = sB[tx * 4 + 1][k];
            float b2 = sB[tx * 4 + 2][k], b3 = sB[tx * 4 + 3][k];
            acc[0][0] += a0 * b0; acc[0][1] += a0 * b1; acc[0][2] += a0 * b2; acc[0][3] += a0 * b3;
            acc[1][0] += a1 * b0; acc[1][1] += a1 * b1; acc[1][2] += a1 * b2; acc[1][3] += a1 * b3;
            acc[2][0] += a2 * b0; acc[2][1] += a2 * b1; acc[2][2] += a2 * b2; acc[2][3] += a2 * b3;
            acc[3][0] += a3 * b0; acc[3][1] += a3 * b1; acc[3][2] += a3 * b2; acc[3][3] += a3 * b3;
        }
        __syncthreads();
    }
    float* dst = g_xnp + (n * SPLIT + sp) * 4096;
    #pragma unroll
    for (int i = 0; i < 4; i++)
        #pragma unroll
        for (int j = 0; j < 4; j++)
            dst[(ty * 4 + i) * 64 + tx * 4 + j] = acc[i][j];
}

// ---------------- k4a: reduce xn partials, GCN (h1 = W1@xn - xn ; h2 = relu(W2@h1)) ----------------
__global__ void __launch_bounds__(256) k4a_gcn(const float* __restrict__ W1,
                                               const float* __restrict__ W2)
{
    int n = blockIdx.x;
    __shared__ float bufA[64][65];   // xn
    __shared__ float bufB[64][65];   // h1
    int tid = threadIdx.x;

    for (int e = tid; e < 4096; e += 256) {
        float s = 0.0f;
        #pragma unroll
        for (int p = 0; p < SPLIT; p++)
            s += g_xnp[(n * SPLIT + p) * 4096 + e];
        bufA[e >> 6][e & 63] = s;
    }
    __syncthreads();
    // h1[s][i] = sum_j W1[i][j]*xn[s][j] - xn[s][i]   (i uniform per warp -> W1 broadcast)
    for (int e = tid; e < 4096; e += 256) {
        int i = e >> 6, s = e & 63;
        float acc = -bufA[s][i];
        #pragma unroll
        for (int j = 0; j < 64; j++) acc = fmaf(W1[i * 64 + j], bufA[s][j], acc);
        bufB[s][i] = acc;
    }
    __syncthreads();
    // h2[i][k] = relu(sum_j W2[i][j]*h1[j][k])
    for (int e = tid; e < 4096; e += 256) {
        int i = e >> 6, k = e & 63;
        float acc = 0.0f;
        #pragma unroll
        for (int j = 0; j < 64; j++) acc = fmaf(W2[i * 64 + j], bufB[j][k], acc);
        g_h2[n * 4096 + e] = fmaxf(acc, 0.0f);
    }
}

// ---------------- k4b: M[o][t] = sum_i We[o][i]*h2[i][t] ----------------
__global__ void __launch_bounds__(256) k4b_M(const float* __restrict__ We)
{
    int n = blockIdx.y;
    int o0 = blockIdx.x * 64;
    __shared__ float h2[64][65];
    int tid = threadIdx.x;
    for (int e = tid; e < 4096; e += 256) h2[e >> 6][e & 63] = g_h2[n * 4096 + e];
    __syncthreads();
    for (int e = tid; e < 4096; e += 256) {
        int o = o0 + (e >> 6), t = e & 63;
        float acc = 0.0f;
        #pragma unroll
        for (int i = 0; i < 64; i++) acc = fmaf(We[o * 64 + i], h2[i][t], acc);
        g_M[n * Cc * Sn + o * 64 + t] = acc;
    }
}

// ---------------- k5: ext = M @ comb  (256x4608x64 per batch) ----------------
__global__ void __launch_bounds__(256) k5_ext()
{
    __shared__ float sM[128][33];
    __shared__ float sC[32][128];
    int n  = blockIdx.z;
    int r0 = blockIdx.y * 128;
    int k0 = blockIdx.x * 128;
    int tid = threadIdx.x, tx = tid & 15, ty = tid >> 4;
    const float* Mn = g_M + n * Cc * Sn;
    const float* Cb = g_t + n * Sn * HWn;
    float acc[8][8] = {};

    for (int c0 = 0; c0 < 64; c0 += 32) {
        #pragma unroll
        for (int t = 0; t < 16; t++) {
            int idx = tid + t * 256;        // 128*32
            int r = idx >> 5, c = idx & 31;
            sM[r][c] = Mn[(r0 + r) * 64 + c0 + c];
        }
        #pragma unroll
        for (int t = 0; t < 16; t++) {
            int idx = tid + t * 256;        // 32*128
            int cc = idx >> 7, k = idx & 127;
            sC[cc][k] = Cb[(c0 + cc) * HWn + k0 + k];
        }
        __syncthreads();
        #pragma unroll
        for (int cc = 0; cc < 32; cc++) {
            float4 b0 = *(const float4*)&sC[cc][tx * 8];
            float4 b1 = *(const float4*)&sC[cc][tx * 8 + 4];
            #pragma unroll
            for (int i = 0; i < 8; i++) {
                float w = sM[ty * 8 + i][cc];
                acc[i][0] += w * b0.x; acc[i][1] += w * b0.y;
                acc[i][2] += w * b0.z; acc[i][3] += w * b0.w;
                acc[i][4] += w * b1.x; acc[i][5] += w * b1.y;
                acc[i][6] += w * b1.z; acc[i][7] += w * b1.w;
            }
        }
        __syncthreads();
    }
    #pragma unroll
    for (int i = 0; i < 8; i++) {
        float* dst = g_ext + (n * Cc + r0 + ty * 8 + i) * HWn + k0 + tx * 8;
        float4 v0 = {acc[i][0], acc[i][1], acc[i][2], acc[i][3]};
        float4 v1 = {acc[i][4], acc[i][5], acc[i][6], acc[i][7]};
        *(float4*)dst = v0; *(float4*)(dst + 4) = v1;
    }
}

// ---------------- k6: per-channel batch mean / inv-std (double accumulation) ----------------
__global__ void __launch_bounds__(256) k6_stats()
{
    int c = blockIdx.x, tid = threadIdx.x;
    __shared__ double rs[256], rq[256];
    double s = 0.0, q = 0.0;
    for (int n = 0; n < Nn; n++) {
        const float* p = g_ext + (n * Cc + c) * HWn;
        for (int i = tid; i < HWn; i += 256) { double v = (double)p[i]; s += v; q += v * v; }
    }
    rs[tid] = s; rq[tid] = q; __syncthreads();
    #pragma unroll
    for (int st = 128; st > 0; st >>= 1) {
        if (tid < st) { rs[tid] += rs[tid + st]; rq[tid] += rq[tid + st]; }
        __syncthreads();
    }
    if (tid == 0) {
        double cnt = (double)Nn * (double)HWn;
        double mean = rs[0] / cnt;
        double var = rq[0] / cnt - mean * mean;
        g_mean[c] = (float)mean;
        g_istd[c] = (float)rsqrt(var + 1e-5);
    }
}

// ---------------- k7: out = x + gamma*(ext-mean)*istd + beta ----------------
__global__ void __launch_bounds__(256) k7_final(const float* __restrict__ x,
                                                const float* __restrict__ gamma,
                                                const float* __restrict__ beta,
                                                float* __restrict__ out)
{
    int i = blockIdx.x * 256 + threadIdx.x;      // float4 index; 4718592 total
    int c = (i / (HWn / 4)) % Cc;
    float m = g_mean[c], is = g_istd[c];
    float g = gamma[c] * is;
    float b = beta[c] - m * g;
    float4 xv = ((const float4*)x)[i];
    float4 ev = ((const float4*)g_ext)[i];
    float4 o;
    o.x = xv.x + ev.x * g + b;
    o.y = xv.y + ev.y * g + b;
    o.z = xv.z + ev.z * g + b;
    o.w = xv.w + ev.w * g + b;
    ((float4*)out)[i] = o;
}

// ---------------- launch ----------------
extern "C" void kernel_launch(void* const* d_in, const int* in_sizes, int n_in,
                              void* d_out, int out_size)
{
    const float* x     = (const float*)d_in[0];
    const float* edge  = (const float*)d_in[1];
    const float* Ws    = (const float*)d_in[2];
    const float* bs    = (const float*)d_in[3];
    const float* Wp    = (const float*)d_in[4];
    const float* bp    = (const float*)d_in[5];
    const float* W1    = (const float*)d_in[6];
    const float* W2    = (const float*)d_in[7];
    const float* We    = (const float*)d_in[8];
    const float* gamma = (const float*)d_in[9];
    const float* beta  = (const float*)d_in[10];
    float* out = (float*)d_out;

    k1_proj   <<<dim3(HWn / 128, Nn), 256>>>(x, edge, Ws, bs, Wp, bp);
    k2_softmax<<<Nn * Sn, 256>>>();
    k3_xn     <<<dim3(SPLIT, Nn), 256>>>();
    k4a_gcn   <<<Nn, 256>>>(W1, W2);
    k4b_M     <<<dim3(Cc / 64, Nn), 256>>>(We);
    k5_ext    <<<dim3(HWn / 128, 2, Nn), 256>>>();
    k6_stats  <<<Cc, 256>>>();
    k7_final  <<<(Nn * Cc * HWn / 4) / 256, 256>>>(x, gamma, beta, out);
}

// round 3
// speedup vs baseline: 1.4999x; 1.4999x over previous
#include <cuda_runtime.h>
#include <cstdint>

#define Nn   16
#define Cc   256
#define HWn  4608
#define Sn   64
#define SPLIT 24
#define KCH  (HWn / SPLIT)   // 192
#define NT   128

// ---------------- scratch (device globals; no allocs allowed) ----------------
__device__ __align__(16) float g_xs [Nn * Sn * HWn];
__device__ __align__(16) float g_t  [Nn * Sn * HWn];
__device__ __align__(16) float g_xnp[Nn * SPLIT * Sn * Sn];
__device__ __align__(16) float g_xn [Nn * Sn * Sn];
__device__ __align__(16) float g_h2 [Nn * Sn * Sn];
__device__ __align__(16) float g_M  [Nn * Cc * Sn];
__device__ __align__(16) float g_ext[Nn * Cc * HWn];
__device__ float g_mean[Cc];
__device__ float g_istd[Cc];

// ---------------- mma helpers ----------------
__device__ __forceinline__ uint32_t f2tf32(float f) {
    uint32_t u;
    asm("cvt.rna.tf32.f32 %0, %1;" : "=r"(u) : "f"(f));
    return u;
}
__device__ __forceinline__ void mma_tf32(float* d, const uint32_t* a, const uint32_t* b) {
    asm volatile(
        "mma.sync.aligned.m16n8k8.row.col.f32.tf32.tf32.f32 "
        "{%0,%1,%2,%3}, {%4,%5,%6,%7}, {%8,%9}, {%0,%1,%2,%3};"
        : "+f"(d[0]), "+f"(d[1]), "+f"(d[2]), "+f"(d[3])
        : "r"(a[0]), "r"(a[1]), "r"(a[2]), "r"(a[3]), "r"(b[0]), "r"(b[1]));
}

// A smem: [m][36] (bank = 4g+t4, conflict-free frag loads)
// B smem: [k][136] (bank = 8t4+g, conflict-free frag loads)
#define SA_STRIDE 36
#define SB_STRIDE 136

// ================= k1: D[128, 128] = [Ws;Wp](128x256) @ x[n](256 x hw-tile) =========
__global__ void __launch_bounds__(256) k1_mma(
    const float* __restrict__ x, const float* __restrict__ edge,
    const float* __restrict__ Ws, const float* __restrict__ bs,
    const float* __restrict__ Wp, const float* __restrict__ bp)
{
    __shared__ uint32_t sA[128 * SA_STRIDE];   // 18432 B
    __shared__ uint32_t sB[32 * SB_STRIDE];    // 17408 B
    const int n = blockIdx.y, k0 = blockIdx.x * NT;
    const int tid = threadIdx.x, wid = tid >> 5, lane = tid & 31;
    const int wm = wid >> 2, wn = wid & 3;
    const int g = lane >> 2, t4 = lane & 3;
    float acc[4][4][4] = {};
    const float* xb = x + (size_t)n * Cc * HWn + k0;

    #pragma unroll 1
    for (int ch = 0; ch < 8; ch++) {
        const int c0 = ch * 32;
        // A fill: 128 rows x 32 k
        #pragma unroll
        for (int it = 0; it < 4; it++) {
            int idx = tid + it * 256;
            int m = idx >> 3, k4 = idx & 7;
            const float* src = ((m < 64) ? (Ws + m * 256) : (Wp + (m - 64) * 256)) + c0 + k4 * 4;
            float4 v = *(const float4*)src;
            uint4 u = {f2tf32(v.x), f2tf32(v.y), f2tf32(v.z), f2tf32(v.w)};
            *(uint4*)&sA[m * SA_STRIDE + k4 * 4] = u;
        }
        // B fill: 32 k-rows x 128 n (direct coalesced copy of x)
        #pragma unroll
        for (int it = 0; it < 4; it++) {
            int idx = tid + it * 256;
            int k = idx >> 5, n4 = idx & 31;
            float4 v = *(const float4*)(xb + (size_t)(c0 + k) * HWn + n4 * 4);
            uint4 u = {f2tf32(v.x), f2tf32(v.y), f2tf32(v.z), f2tf32(v.w)};
            *(uint4*)&sB[k * SB_STRIDE + n4 * 4] = u;
        }
        __syncthreads();
        #pragma unroll
        for (int ks = 0; ks < 4; ks++) {
            const int kb = ks * 8;
            uint32_t a[4][4], b[4][2];
            #pragma unroll
            for (int mt = 0; mt < 4; mt++) {
                int m = wm * 64 + mt * 16;
                a[mt][0] = sA[(m + g) * SA_STRIDE + kb + t4];
                a[mt][1] = sA[(m + g + 8) * SA_STRIDE + kb + t4];
                a[mt][2] = sA[(m + g) * SA_STRIDE + kb + t4 + 4];
                a[mt][3] = sA[(m + g + 8) * SA_STRIDE + kb + t4 + 4];
            }
            #pragma unroll
            for (int nt = 0; nt < 4; nt++) {
                int nn = wn * 32 + nt * 8;
                b[nt][0] = sB[(kb + t4) * SB_STRIDE + nn + g];
                b[nt][1] = sB[(kb + t4 + 4) * SB_STRIDE + nn + g];
            }
            #pragma unroll
            for (int mt = 0; mt < 4; mt++)
                #pragma unroll
                for (int nt = 0; nt < 4; nt++)
                    mma_tf32(acc[mt][nt], a[mt], b[nt]);
        }
        __syncthreads();
    }

    // epilogue: direct float2 stores (each 4-lane group = one 32B sector)
    const int nbase = k0 + wn * 32 + 2 * t4;
    if (wm == 0) {
        #pragma unroll
        for (int mt = 0; mt < 4; mt++) {
            int s0 = mt * 16 + g;
            float bv0 = bs[s0], bv1 = bs[s0 + 8];
            float* r0p = g_xs + (size_t)(n * 64 + s0) * HWn;
            float* r1p = r0p + (size_t)8 * HWn;
            #pragma unroll
            for (int nt = 0; nt < 4; nt++) {
                int col = nbase + nt * 8;
                float2 v0 = {acc[mt][nt][0] + bv0, acc[mt][nt][1] + bv0};
                float2 v1 = {acc[mt][nt][2] + bv1, acc[mt][nt][3] + bv1};
                *(float2*)(r0p + col) = v0;
                *(float2*)(r1p + col) = v1;
            }
        }
    } else {
        const float* e0p = edge + (size_t)(n * 2) * HWn;
        const float* e1p = e0p + HWn;
        float2 gate[4];
        #pragma unroll
        for (int nt = 0; nt < 4; nt++) {
            int col = nbase + nt * 8;
            float2 e0 = *(const float2*)(e0p + col);
            float2 e1 = *(const float2*)(e1p + col);
            gate[nt].x = 2.0f - 1.0f / (1.0f + __expf(e1.x - e0.x));
            gate[nt].y = 2.0f - 1.0f / (1.0f + __expf(e1.y - e0.y));
        }
        #pragma unroll
        for (int mt = 0; mt < 4; mt++) {
            int s0 = mt * 16 + g;
            float bv0 = bp[s0], bv1 = bp[s0 + 8];
            float* r0p = g_t + (size_t)(n * 64 + s0) * HWn;
            float* r1p = r0p + (size_t)8 * HWn;
            #pragma unroll
            for (int nt = 0; nt < 4; nt++) {
                int col = nbase + nt * 8;
                float2 v0 = {(acc[mt][nt][0] + bv0) * gate[nt].x,
                             (acc[mt][nt][1] + bv0) * gate[nt].y};
                float2 v1 = {(acc[mt][nt][2] + bv1) * gate[nt].x,
                             (acc[mt][nt][3] + bv1) * gate[nt].y};
                *(float2*)(r0p + col) = v0;
                *(float2*)(r1p + col) = v1;
            }
        }
    }
}

// ================= k5: ext[r-band, hw-tile] = M(128x64) @ comb(64 x 128) ============
__global__ void __launch_bounds__(256) k5_mma()
{
    __shared__ uint32_t sA[128 * SA_STRIDE];
    __shared__ uint32_t sB[32 * SB_STRIDE];
    const int n = blockIdx.z, r0 = blockIdx.y * 128, k0 = blockIdx.x * NT;
    const int tid = threadIdx.x, wid = tid >> 5, lane = tid & 31;
    const int wm = wid >> 2, wn = wid & 3;
    const int g = lane >> 2, t4 = lane & 3;
    float acc[4][4][4] = {};
    const float* Mb = g_M + (size_t)n * Cc * Sn;
    const float* Cb = g_t + (size_t)n * Sn * HWn + k0;

    #pragma unroll 1
    for (int ch = 0; ch < 2; ch++) {
        const int c0 = ch * 32;
        #pragma unroll
        for (int it = 0; it < 4; it++) {
            int idx = tid + it * 256;
            int m = idx >> 3, k4 = idx & 7;
            float4 v = *(const float4*)(Mb + (size_t)(r0 + m) * 64 + c0 + k4 * 4);
            uint4 u = {f2tf32(v.x), f2tf32(v.y), f2tf32(v.z), f2tf32(v.w)};
            *(uint4*)&sA[m * SA_STRIDE + k4 * 4] = u;
        }
        #pragma unroll
        for (int it = 0; it < 4; it++) {
            int idx = tid + it * 256;
            int k = idx >> 5, n4 = idx & 31;
            float4 v = *(const float4*)(Cb + (size_t)(c0 + k) * HWn + n4 * 4);
            uint4 u = {f2tf32(v.x), f2tf32(v.y), f2tf32(v.z), f2tf32(v.w)};
            *(uint4*)&sB[k * SB_STRIDE + n4 * 4] = u;
        }
        __syncthreads();
        #pragma unroll
        for (int ks = 0; ks < 4; ks++) {
            const int kb = ks * 8;
            uint32_t a[4][4], b[4][2];
            #pragma unroll
            for (int mt = 0; mt < 4; mt++) {
                int m = wm * 64 + mt * 16;
                a[mt][0] = sA[(m + g) * SA_STRIDE + kb + t4];
                a[mt][1] = sA[(m + g + 8) * SA_STRIDE + kb + t4];
                a[mt][2] = sA[(m + g) * SA_STRIDE + kb + t4 + 4];
                a[mt][3] = sA[(m + g + 8) * SA_STRIDE + kb + t4 + 4];
            }
            #pragma unroll
            for (int nt = 0; nt < 4; nt++) {
                int nn = wn * 32 + nt * 8;
                b[nt][0] = sB[(kb + t4) * SB_STRIDE + nn + g];
                b[nt][1] = sB[(kb + t4 + 4) * SB_STRIDE + nn + g];
            }
            #pragma unroll
            for (int mt = 0; mt < 4; mt++)
                #pragma unroll
                for (int nt = 0; nt < 4; nt++)
                    mma_tf32(acc[mt][nt], a[mt], b[nt]);
        }
        __syncthreads();
    }

    const int nbase = k0 + wn * 32 + 2 * t4;
    #pragma unroll
    for (int mt = 0; mt < 4; mt++) {
        int r = r0 + wm * 64 + mt * 16 + g;
        float* r0p = g_ext + (size_t)(n * Cc + r) * HWn;
        float* r1p = r0p + (size_t)8 * HWn;
        #pragma unroll
        for (int nt = 0; nt < 4; nt++) {
            int col = nbase + nt * 8;
            float2 v0 = {acc[mt][nt][0], acc[mt][nt][1]};
            float2 v1 = {acc[mt][nt][2], acc[mt][nt][3]};
            *(float2*)(r0p + col) = v0;
            *(float2*)(r1p + col) = v1;
        }
    }
}

// ================= k3: xn partials = xs(64xK) @ comb(64xK)^T over K-chunk ============
__global__ void __launch_bounds__(256) k3_mma()
{
    __shared__ uint32_t sA[64 * SA_STRIDE];   // xs  [m][k]
    __shared__ uint32_t sB[64 * SA_STRIDE];   // comb [n][k] (B col-major frag native)
    const int sp = blockIdx.x, n = blockIdx.y;
    const int koff = sp * KCH;
    const int tid = threadIdx.x, wid = tid >> 5, lane = tid & 31;
    const int wm = wid >> 2, wn = wid & 3;       // 2 x 4
    const int g = lane >> 2, t4 = lane & 3;
    float acc[2][2][4] = {};
    const float* A = g_xs + (size_t)n * Sn * HWn + koff;
    const float* B = g_t  + (size_t)n * Sn * HWn + koff;

    #pragma unroll 1
    for (int ch = 0; ch < 6; ch++) {
        const int c0 = ch * 32;
        #pragma unroll
        for (int it = 0; it < 2; it++) {
            int idx = tid + it * 256;
            int m = idx >> 3, k4 = idx & 7;
            float4 va = *(const float4*)(A + (size_t)m * HWn + c0 + k4 * 4);
            float4 vb = *(const float4*)(B + (size_t)m * HWn + c0 + k4 * 4);
            uint4 ua = {f2tf32(va.x), f2tf32(va.y), f2tf32(va.z), f2tf32(va.w)};
            uint4 ub = {f2tf32(vb.x), f2tf32(vb.y), f2tf32(vb.z), f2tf32(vb.w)};
            *(uint4*)&sA[m * SA_STRIDE + k4 * 4] = ua;
            *(uint4*)&sB[m * SA_STRIDE + k4 * 4] = ub;
        }
        __syncthreads();
        #pragma unroll
        for (int ks = 0; ks < 4; ks++) {
            const int kb = ks * 8;
            uint32_t a[2][4], b[2][2];
            #pragma unroll
            for (int mt = 0; mt < 2; mt++) {
                int m = wm * 32 + mt * 16;
                a[mt][0] = sA[(m + g) * SA_STRIDE + kb + t4];
                a[mt][1] = sA[(m + g + 8) * SA_STRIDE + kb + t4];
                a[mt][2] = sA[(m + g) * SA_STRIDE + kb + t4 + 4];
                a[mt][3] = sA[(m + g + 8) * SA_STRIDE + kb + t4 + 4];
            }
            #pragma unroll
            for (int nt = 0; nt < 2; nt++) {
                int nn = wn * 16 + nt * 8;
                b[nt][0] = sB[(nn + g) * SA_STRIDE + kb + t4];
                b[nt][1] = sB[(nn + g) * SA_STRIDE + kb + t4 + 4];
            }
            #pragma unroll
            for (int mt = 0; mt < 2; mt++)
                #pragma unroll
                for (int nt = 0; nt < 2; nt++)
                    mma_tf32(acc[mt][nt], a[mt], b[nt]);
        }
        __syncthreads();
    }

    float* dst = g_xnp + (size_t)(n * SPLIT + sp) * 4096;
    #pragma unroll
    for (int mt = 0; mt < 2; mt++) {
        int s = wm * 32 + mt * 16 + g;
        #pragma unroll
        for (int nt = 0; nt < 2; nt++) {
            int t = wn * 16 + nt * 8 + 2 * t4;
            *(float2*)(dst + s * 64 + t)       = make_float2(acc[mt][nt][0], acc[mt][nt][1]);
            *(float2*)(dst + (s + 8) * 64 + t) = make_float2(acc[mt][nt][2], acc[mt][nt][3]);
        }
    }
}

// ---------------- k3r: reduce split-K partials to g_xn ----------------
__global__ void __launch_bounds__(256) k3r_reduce()
{
    int i = blockIdx.x * 256 + threadIdx.x;      // float4 index over Nn*4096/4 = 16384
    int n = i >> 10, e4 = i & 1023;
    float4 s = {0.f, 0.f, 0.f, 0.f};
    #pragma unroll
    for (int p = 0; p < SPLIT; p++) {
        float4 v = *(const float4*)(g_xnp + (size_t)(n * SPLIT + p) * 4096 + e4 * 4);
        s.x += v.x; s.y += v.y; s.z += v.z; s.w += v.w;
    }
    *(float4*)(g_xn + (size_t)n * 4096 + e4 * 4) = s;
}

// ---------------- k2: row softmax over HW (1024 rows, in place on g_t) ----------------
__global__ void __launch_bounds__(256) k2_softmax()
{
    int row = blockIdx.x;
    float* p = g_t + (size_t)row * HWn;
    int tid = threadIdx.x;
    __shared__ float red[256];
    float v[18];
    float m = -1e30f;
    #pragma unroll
    for (int t = 0; t < 18; t++) { v[t] = p[tid + t * 256]; m = fmaxf(m, v[t]); }
    red[tid] = m; __syncthreads();
    #pragma unroll
    for (int s = 128; s > 0; s >>= 1) {
        if (tid < s) red[tid] = fmaxf(red[tid], red[tid + s]);
        __syncthreads();
    }
    m = red[0];
    __syncthreads();
    float sum = 0.0f;
    #pragma unroll
    for (int t = 0; t < 18; t++) { v[t] = __expf(v[t] - m); sum += v[t]; }
    red[tid] = sum; __syncthreads();
    #pragma unroll
    for (int s = 128; s > 0; s >>= 1) {
        if (tid < s) red[tid] += red[tid + s];
        __syncthreads();
    }
    float inv = 1.0f / red[0];
    #pragma unroll
    for (int t = 0; t < 18; t++) p[tid + t * 256] = v[t] * inv;
}

// ---------------- k4a: GCN from g_xn ----------------
__global__ void __launch_bounds__(256) k4a_gcn(const float* __restrict__ W1,
                                               const float* __restrict__ W2)
{
    int n = blockIdx.x;
    __shared__ float bufA[64][65];
    __shared__ float bufB[64][65];
    int tid = threadIdx.x, wid = tid >> 5, lane = tid & 31;

    for (int e = tid; e < 4096; e += 256) bufA[e >> 6][e & 63] = g_xn[(size_t)n * 4096 + e];
    __syncthreads();
    #pragma unroll
    for (int it = 0; it < 8; it++) {
        int i = wid + it * 8;
        #pragma unroll
        for (int h = 0; h < 2; h++) {
            int s = lane + h * 32;
            float acc = -bufA[s][i];
            #pragma unroll
            for (int j = 0; j < 64; j++) acc = fmaf(__ldg(&W1[i * 64 + j]), bufA[s][j], acc);
            bufB[s][i] = acc;
        }
    }
    __syncthreads();
    #pragma unroll
    for (int it = 0; it < 8; it++) {
        int i = wid + it * 8;
        #pragma unroll
        for (int h = 0; h < 2; h++) {
            int k = lane + h * 32;
            float acc = 0.0f;
            #pragma unroll
            for (int j = 0; j < 64; j++) acc = fmaf(__ldg(&W2[i * 64 + j]), bufB[j][k], acc);
            g_h2[(size_t)n * 4096 + i * 64 + k] = fmaxf(acc, 0.0f);
        }
    }
}

// ---------------- k4b: M[o][t] = sum_i We[o][i]*h2[i][t] ----------------
__global__ void __launch_bounds__(256) k4b_M(const float* __restrict__ We)
{
    int n = blockIdx.y, o0 = blockIdx.x * 64;
    __shared__ float h2s[64][65];
    int tid = threadIdx.x, wid = tid >> 5, lane = tid & 31;
    for (int e = tid; e < 4096; e += 256) h2s[e >> 6][e & 63] = g_h2[(size_t)n * 4096 + e];
    __syncthreads();
    #pragma unroll
    for (int it = 0; it < 8; it++) {
        int o = o0 + wid + it * 8;
        #pragma unroll
        for (int h = 0; h < 2; h++) {
            int t = lane + h * 32;
            float acc = 0.0f;
            #pragma unroll
            for (int j = 0; j < 64; j++) acc = fmaf(__ldg(&We[o * 64 + j]), h2s[j][t], acc);
            g_M[(size_t)n * Cc * Sn + o * 64 + t] = acc;
        }
    }
}

// ---------------- k6: per-channel batch mean / inv-std ----------------
__global__ void __launch_bounds__(256) k6_stats()
{
    int c = blockIdx.x, tid = threadIdx.x;
    __shared__ double rs[256], rq[256];
    double s = 0.0, q = 0.0;
    for (int n = 0; n < Nn; n++) {
        const float* p = g_ext + (size_t)(n * Cc + c) * HWn;
        for (int i = tid; i < HWn; i += 256) { double v = (double)p[i]; s += v; q += v * v; }
    }
    rs[tid] = s; rq[tid] = q; __syncthreads();
    #pragma unroll
    for (int st = 128; st > 0; st >>= 1) {
        if (tid < st) { rs[tid] += rs[tid + st]; rq[tid] += rq[tid + st]; }
        __syncthreads();
    }
    if (tid == 0) {
        double cnt = (double)Nn * (double)HWn;
        double mean = rs[0] / cnt;
        double var = rq[0] / cnt - mean * mean;
        g_mean[c] = (float)mean;
        g_istd[c] = (float)rsqrt(var + 1e-5);
    }
}

// ---------------- k7: out = x + gamma*(ext-mean)*istd + beta ----------------
__global__ void __launch_bounds__(256) k7_final(const float* __restrict__ x,
                                                const float* __restrict__ gamma,
                                                const float* __restrict__ beta,
                                                float* __restrict__ out)
{
    int i = blockIdx.x * 256 + threadIdx.x;
    int c = (i / (HWn / 4)) % Cc;
    float m = g_mean[c], is = g_istd[c];
    float g = gamma[c] * is;
    float b = beta[c] - m * g;
    float4 xv = ((const float4*)x)[i];
    float4 ev = ((const float4*)g_ext)[i];
    float4 o;
    o.x = xv.x + ev.x * g + b;
    o.y = xv.y + ev.y * g + b;
    o.z = xv.z + ev.z * g + b;
    o.w = xv.w + ev.w * g + b;
    ((float4*)out)[i] = o;
}

// ---------------- launch ----------------
extern "C" void kernel_launch(void* const* d_in, const int* in_sizes, int n_in,
                              void* d_out, int out_size)
{
    const float* x     = (const float*)d_in[0];
    const float* edge  = (const float*)d_in[1];
    const float* Ws    = (const float*)d_in[2];
    const float* bs    = (const float*)d_in[3];
    const float* Wp    = (const float*)d_in[4];
    const float* bp    = (const float*)d_in[5];
    const float* W1    = (const float*)d_in[6];
    const float* W2    = (const float*)d_in[7];
    const float* We    = (const float*)d_in[8];
    const float* gamma = (const float*)d_in[9];
    const float* beta  = (const float*)d_in[10];
    float* out = (float*)d_out;

    k1_mma    <<<dim3(HWn / NT, Nn), 256>>>(x, edge, Ws, bs, Wp, bp);
    k2_softmax<<<Nn * Sn, 256>>>();
    k3_mma    <<<dim3(SPLIT, Nn), 256>>>();
    k3r_reduce<<<Nn * 4096 / 4 / 256, 256>>>();
    k4a_gcn   <<<Nn, 256>>>(W1, W2);
    k4b_M     <<<dim3(Cc / 64, Nn), 256>>>(We);
    k5_mma    <<<dim3(HWn / NT, 2, Nn), 256>>>();
    k6_stats  <<<Cc, 256>>>();
    k7_final  <<<(Nn * Cc * HWn / 4) / 256, 256>>>(x, gamma, beta, out);
}

// round 4
// speedup vs baseline: 2.6779x; 1.7854x over previous
#include <cuda_runtime.h>
#include <cstdint>

#define Nn   16
#define Cc   256
#define HWn  4608
#define Sn   64
#define SPLIT 12
#define KCH  (HWn / SPLIT)   // 384
#define NT   128
#define NTILE (HWn / NT)     // 36

// ---------------- scratch (device globals; no allocs allowed) ----------------
__device__ __align__(16) float g_xs [Nn * Sn * HWn];
__device__ __align__(16) float g_t  [Nn * Sn * HWn];          // raw gated t (pre-softmax)
__device__ __align__(16) float g_xnp[Nn * SPLIT * Sn * Sn];
__device__ __align__(16) float g_xn [Nn * Sn * Sn];
__device__ __align__(16) float g_h2 [Nn * Sn * Sn];
__device__ __align__(16) float g_M  [Nn * Cc * Sn];
__device__ __align__(16) float g_ext[Nn * Cc * HWn];
__device__ __align__(16) float g_pm [Nn * NTILE * Sn];        // softmax partial max
__device__ __align__(16) float g_ps [Nn * NTILE * Sn];        // softmax partial sumexp
__device__ float g_rM[Nn * Sn];                                // row max
__device__ float g_rI[Nn * Sn];                                // row 1/sum
__device__ __align__(16) float g_ps1[Nn * 2 * NTILE * 128];   // BN partial sum
__device__ __align__(16) float g_ps2[Nn * 2 * NTILE * 128];   // BN partial sumsq
__device__ float g_mean[Cc];
__device__ float g_istd[Cc];

// ---------------- helpers ----------------
__device__ __forceinline__ uint32_t smem_u32(const void* p) {
    uint32_t a;
    asm("{ .reg .u64 t; cvta.to.shared.u64 t, %1; cvt.u32.u64 %0, t; }" : "=r"(a) : "l"(p));
    return a;
}
__device__ __forceinline__ uint32_t f2tf32(float f) {
    uint32_t u;
    asm("cvt.rna.tf32.f32 %0, %1;" : "=r"(u) : "f"(f));
    return u;
}
__device__ __forceinline__ void mma_tf32(float* d, const uint32_t* a, const uint32_t* b) {
    asm volatile(
        "mma.sync.aligned.m16n8k8.row.col.f32.tf32.tf32.f32 "
        "{%0,%1,%2,%3}, {%4,%5,%6,%7}, {%8,%9}, {%0,%1,%2,%3};"
        : "+f"(d[0]), "+f"(d[1]), "+f"(d[2]), "+f"(d[3])
        : "r"(a[0]), "r"(a[1]), "r"(a[2]), "r"(a[3]), "r"(b[0]), "r"(b[1]));
}
__device__ __forceinline__ void cp16(uint32_t dst, const void* src) {
    asm volatile("cp.async.ca.shared.global [%0], [%1], 16;" :: "r"(dst), "l"(src));
}
#define CP_COMMIT()  asm volatile("cp.async.commit_group;" ::: "memory")
#define CP_WAIT0()   asm volatile("cp.async.wait_group 0;" ::: "memory")
#define CP_WAIT1()   asm volatile("cp.async.wait_group 1;" ::: "memory")

#define SA_STRIDE 36
#define SB_STRIDE 136
// dynamic smem float offsets
#define OFF_A0 0
#define OFF_A1 4608
#define OFF_B0 9216
#define OFF_B1 13568
#define GEMM_SMEM_BYTES (17920 * 4)   // 71680

// ================= k1: [xs;t](128 x 128cols) = [Ws;Wp](128x256) @ x-tile ============
// also emits per-(row,tile) softmax partials (max, sumexp) for the t half.
__global__ void __launch_bounds__(256) k1_mma(
    const float* __restrict__ x, const float* __restrict__ edge,
    const float* __restrict__ Ws, const float* __restrict__ bs,
    const float* __restrict__ Wp, const float* __restrict__ bp)
{
    extern __shared__ float smf[];
    const int n = blockIdx.y, tileX = blockIdx.x, k0 = tileX * NT;
    const int tid = threadIdx.x, wid = tid >> 5, lane = tid & 31;
    const int wm = wid >> 2, wn = wid & 3;
    const int g = lane >> 2, t4 = lane & 3;
    const uint32_t sb = smem_u32(smf);
    float acc[4][4][4] = {};
    const float* xb = x + (size_t)n * Cc * HWn + k0;

    auto issueA = [&](int ch, int buf) {
        const uint32_t base = sb + (buf ? OFF_A1 : OFF_A0) * 4;
        #pragma unroll
        for (int it = 0; it < 4; it++) {
            int idx = tid + it * 256;
            int m = idx >> 3, k4 = idx & 7;
            const float* src = ((m < 64) ? (Ws + m * 256) : (Wp + (m - 64) * 256))
                               + ch * 32 + k4 * 4;
            cp16(base + (uint32_t)(m * SA_STRIDE + k4 * 4) * 4, src);
        }
    };
    auto issueB = [&](int ch, int buf) {
        const uint32_t base = sb + (buf ? OFF_B1 : OFF_B0) * 4;
        #pragma unroll
        for (int it = 0; it < 4; it++) {
            int idx = tid + it * 256;
            int k = idx >> 5, n4 = idx & 31;
            cp16(base + (uint32_t)(k * SB_STRIDE + n4 * 4) * 4,
                 xb + (size_t)(ch * 32 + k) * HWn + n4 * 4);
        }
    };

    issueA(0, 0); issueB(0, 0); CP_COMMIT();

    #pragma unroll 1
    for (int ch = 0; ch < 8; ch++) {
        if (ch < 7) { issueA(ch + 1, (ch + 1) & 1); issueB(ch + 1, (ch + 1) & 1); CP_COMMIT(); CP_WAIT1(); }
        else CP_WAIT0();
        __syncthreads();
        const float* fA = smf + ((ch & 1) ? OFF_A1 : OFF_A0);
        const float* fB = smf + ((ch & 1) ? OFF_B1 : OFF_B0);
        #pragma unroll
        for (int ks = 0; ks < 4; ks++) {
            const int kb = ks * 8;
            uint32_t a[4][4], b[4][2];
            #pragma unroll
            for (int mt = 0; mt < 4; mt++) {
                int m = wm * 64 + mt * 16;
                a[mt][0] = f2tf32(fA[(m + g) * SA_STRIDE + kb + t4]);
                a[mt][1] = f2tf32(fA[(m + g + 8) * SA_STRIDE + kb + t4]);
                a[mt][2] = f2tf32(fA[(m + g) * SA_STRIDE + kb + t4 + 4]);
                a[mt][3] = f2tf32(fA[(m + g + 8) * SA_STRIDE + kb + t4 + 4]);
            }
            #pragma unroll
            for (int nt = 0; nt < 4; nt++) {
                int nn = wn * 32 + nt * 8;
                b[nt][0] = f2tf32(fB[(kb + t4) * SB_STRIDE + nn + g]);
                b[nt][1] = f2tf32(fB[(kb + t4 + 4) * SB_STRIDE + nn + g]);
            }
            #pragma unroll
            for (int mt = 0; mt < 4; mt++)
                #pragma unroll
                for (int nt = 0; nt < 4; nt++)
                    mma_tf32(acc[mt][nt], a[mt], b[nt]);
        }
        __syncthreads();
    }

    const int nbase = k0 + wn * 32 + 2 * t4;
    float* sPm = smf;          // [4][64]
    float* sPs = smf + 256;    // [4][64]

    if (wm == 0) {
        // xs half: add bias, store
        #pragma unroll
        for (int mt = 0; mt < 4; mt++) {
            int s0 = mt * 16 + g;
            float bv0 = bs[s0], bv1 = bs[s0 + 8];
            float* r0p = g_xs + (size_t)(n * 64 + s0) * HWn;
            float* r1p = r0p + (size_t)8 * HWn;
            #pragma unroll
            for (int nt = 0; nt < 4; nt++) {
                int col = nbase + nt * 8;
                *(float2*)(r0p + col) = make_float2(acc[mt][nt][0] + bv0, acc[mt][nt][1] + bv0);
                *(float2*)(r1p + col) = make_float2(acc[mt][nt][2] + bv1, acc[mt][nt][3] + bv1);
            }
        }
    } else {
        // t half: bias + gate, store raw, then per-row tile max
        const float* e0p = edge + (size_t)(n * 2) * HWn;
        const float* e1p = e0p + HWn;
        float2 gate[4];
        #pragma unroll
        for (int nt = 0; nt < 4; nt++) {
            int col = nbase + nt * 8;
            float2 e0 = *(const float2*)(e0p + col);
            float2 e1 = *(const float2*)(e1p + col);
            gate[nt].x = 2.0f - 1.0f / (1.0f + __expf(e1.x - e0.x));
            gate[nt].y = 2.0f - 1.0f / (1.0f + __expf(e1.y - e0.y));
        }
        #pragma unroll
        for (int mt = 0; mt < 4; mt++) {
            int s0 = mt * 16 + g;
            float bv0 = bp[s0], bv1 = bp[s0 + 8];
            float* r0p = g_t + (size_t)(n * 64 + s0) * HWn;
            float* r1p = r0p + (size_t)8 * HWn;
            float mA = -1e30f, mB = -1e30f;
            #pragma unroll
            for (int nt = 0; nt < 4; nt++) {
                int col = nbase + nt * 8;
                float v0 = (acc[mt][nt][0] + bv0) * gate[nt].x;
                float v1 = (acc[mt][nt][1] + bv0) * gate[nt].y;
                float v2 = (acc[mt][nt][2] + bv1) * gate[nt].x;
                float v3 = (acc[mt][nt][3] + bv1) * gate[nt].y;
                acc[mt][nt][0] = v0; acc[mt][nt][1] = v1;
                acc[mt][nt][2] = v2; acc[mt][nt][3] = v3;
                *(float2*)(r0p + col) = make_float2(v0, v1);
                *(float2*)(r1p + col) = make_float2(v2, v3);
                mA = fmaxf(mA, fmaxf(v0, v1));
                mB = fmaxf(mB, fmaxf(v2, v3));
            }
            mA = fmaxf(mA, __shfl_xor_sync(0xffffffffu, mA, 1));
            mA = fmaxf(mA, __shfl_xor_sync(0xffffffffu, mA, 2));
            mB = fmaxf(mB, __shfl_xor_sync(0xffffffffu, mB, 1));
            mB = fmaxf(mB, __shfl_xor_sync(0xffffffffu, mB, 2));
            if (t4 == 0) { sPm[wn * 64 + s0] = mA; sPm[wn * 64 + s0 + 8] = mB; }
        }
    }
    __syncthreads();
    if (wm == 1) {
        #pragma unroll
        for (int mt = 0; mt < 4; mt++) {
            int rA = mt * 16 + g, rB = rA + 8;
            float MA = fmaxf(fmaxf(sPm[rA], sPm[64 + rA]), fmaxf(sPm[128 + rA], sPm[192 + rA]));
            float MB = fmaxf(fmaxf(sPm[rB], sPm[64 + rB]), fmaxf(sPm[128 + rB], sPm[192 + rB]));
            float sA = 0.f, sB = 0.f;
            #pragma unroll
            for (int nt = 0; nt < 4; nt++) {
                sA += __expf(acc[mt][nt][0] - MA) + __expf(acc[mt][nt][1] - MA);
                sB += __expf(acc[mt][nt][2] - MB) + __expf(acc[mt][nt][3] - MB);
            }
            sA += __shfl_xor_sync(0xffffffffu, sA, 1);
            sA += __shfl_xor_sync(0xffffffffu, sA, 2);
            sB += __shfl_xor_sync(0xffffffffu, sB, 1);
            sB += __shfl_xor_sync(0xffffffffu, sB, 2);
            if (t4 == 0) { sPs[wn * 64 + rA] = sA; sPs[wn * 64 + rB] = sB; }
        }
    }
    __syncthreads();
    if (wm == 1 && wn == 0 && t4 == 0) {
        #pragma unroll
        for (int mt = 0; mt < 4; mt++) {
            #pragma unroll
            for (int h = 0; h < 2; h++) {
                int r = mt * 16 + g + h * 8;
                float M = fmaxf(fmaxf(sPm[r], sPm[64 + r]), fmaxf(sPm[128 + r], sPm[192 + r]));
                float S = sPs[r] + sPs[64 + r] + sPs[128 + r] + sPs[192 + r];
                g_pm[(size_t)(n * NTILE + tileX) * 64 + r] = M;
                g_ps[(size_t)(n * NTILE + tileX) * 64 + r] = S;
            }
        }
    }
}

// ---------------- k2s: merge softmax partials -> row max, row 1/sum ----------------
__global__ void __launch_bounds__(256) k2s_merge()
{
    int idx = blockIdx.x * 256 + threadIdx.x;     // 1024 rows
    int n = idx >> 6, s = idx & 63;
    float M = -1e30f;
    #pragma unroll
    for (int t = 0; t < NTILE; t++)
        M = fmaxf(M, g_pm[(size_t)(n * NTILE + t) * 64 + s]);
    float S = 0.f;
    #pragma unroll
    for (int t = 0; t < NTILE; t++)
        S += g_ps[(size_t)(n * NTILE + t) * 64 + s] *
             __expf(g_pm[(size_t)(n * NTILE + t) * 64 + s] - M);
    g_rM[idx] = M;
    g_rI[idx] = 1.0f / S;
}

// ================= k3: xn partials = xs(64xK) @ comb(64xK)^T, exp on the fly =========
__global__ void __launch_bounds__(256) k3_mma()
{
    __shared__ uint32_t sA[64 * SA_STRIDE];
    __shared__ uint32_t sB[64 * SA_STRIDE];
    const int sp = blockIdx.x, n = blockIdx.y;
    const int koff = sp * KCH;
    const int tid = threadIdx.x, wid = tid >> 5, lane = tid & 31;
    const int wm = wid >> 2, wn = wid & 3;
    const int g = lane >> 2, t4 = lane & 3;
    float acc[2][2][4] = {};
    const float* A = g_xs + (size_t)n * Sn * HWn + koff;
    const float* B = g_t  + (size_t)n * Sn * HWn + koff;

    #pragma unroll 1
    for (int ch = 0; ch < KCH / 32; ch++) {
        const int c0 = ch * 32;
        #pragma unroll
        for (int it = 0; it < 2; it++) {
            int idx = tid + it * 256;
            int m = idx >> 3, k4 = idx & 7;
            float4 va = *(const float4*)(A + (size_t)m * HWn + c0 + k4 * 4);
            float4 vb = *(const float4*)(B + (size_t)m * HWn + c0 + k4 * 4);
            float Mr = __ldg(&g_rM[n * 64 + m]), Ir = __ldg(&g_rI[n * 64 + m]);
            vb.x = __expf(vb.x - Mr) * Ir; vb.y = __expf(vb.y - Mr) * Ir;
            vb.z = __expf(vb.z - Mr) * Ir; vb.w = __expf(vb.w - Mr) * Ir;
            uint4 ua = {f2tf32(va.x), f2tf32(va.y), f2tf32(va.z), f2tf32(va.w)};
            uint4 ub = {f2tf32(vb.x), f2tf32(vb.y), f2tf32(vb.z), f2tf32(vb.w)};
            *(uint4*)&sA[m * SA_STRIDE + k4 * 4] = ua;
            *(uint4*)&sB[m * SA_STRIDE + k4 * 4] = ub;
        }
        __syncthreads();
        #pragma unroll
        for (int ks = 0; ks < 4; ks++) {
            const int kb = ks * 8;
            uint32_t a[2][4], b[2][2];
            #pragma unroll
            for (int mt = 0; mt < 2; mt++) {
                int m = wm * 32 + mt * 16;
                a[mt][0] = sA[(m + g) * SA_STRIDE + kb + t4];
                a[mt][1] = sA[(m + g + 8) * SA_STRIDE + kb + t4];
                a[mt][2] = sA[(m + g) * SA_STRIDE + kb + t4 + 4];
                a[mt][3] = sA[(m + g + 8) * SA_STRIDE + kb + t4 + 4];
            }
            #pragma unroll
            for (int nt = 0; nt < 2; nt++) {
                int nn = wn * 16 + nt * 8;
                b[nt][0] = sB[(nn + g) * SA_STRIDE + kb + t4];
                b[nt][1] = sB[(nn + g) * SA_STRIDE + kb + t4 + 4];
            }
            #pragma unroll
            for (int mt = 0; mt < 2; mt++)
                #pragma unroll
                for (int nt = 0; nt < 2; nt++)
                    mma_tf32(acc[mt][nt], a[mt], b[nt]);
        }
        __syncthreads();
    }

    float* dst = g_xnp + (size_t)(n * SPLIT + sp) * 4096;
    #pragma unroll
    for (int mt = 0; mt < 2; mt++) {
        int s = wm * 32 + mt * 16 + g;
        #pragma unroll
        for (int nt = 0; nt < 2; nt++) {
            int t = wn * 16 + nt * 8 + 2 * t4;
            *(float2*)(dst + s * 64 + t)       = make_float2(acc[mt][nt][0], acc[mt][nt][1]);
            *(float2*)(dst + (s + 8) * 64 + t) = make_float2(acc[mt][nt][2], acc[mt][nt][3]);
        }
    }
}

// ---------------- k3r: reduce split-K partials ----------------
__global__ void __launch_bounds__(256) k3r_reduce()
{
    int i = blockIdx.x * 256 + threadIdx.x;      // 16384 float4s
    int n = i >> 10, e4 = i & 1023;
    float4 s = {0.f, 0.f, 0.f, 0.f};
    #pragma unroll
    for (int p = 0; p < SPLIT; p++) {
        float4 v = *(const float4*)(g_xnp + (size_t)(n * SPLIT + p) * 4096 + e4 * 4);
        s.x += v.x; s.y += v.y; s.z += v.z; s.w += v.w;
    }
    *(float4*)(g_xn + (size_t)n * 4096 + e4 * 4) = s;
}

// ---------------- k4a: GCN ----------------
__global__ void __launch_bounds__(256) k4a_gcn(const float* __restrict__ W1,
                                               const float* __restrict__ W2)
{
    int n = blockIdx.x;
    __shared__ float bufA[64][65];
    __shared__ float bufB[64][65];
    int tid = threadIdx.x, wid = tid >> 5, lane = tid & 31;

    for (int e = tid; e < 4096; e += 256) bufA[e >> 6][e & 63] = g_xn[(size_t)n * 4096 + e];
    __syncthreads();
    #pragma unroll
    for (int it = 0; it < 8; it++) {
        int i = wid + it * 8;
        #pragma unroll
        for (int h = 0; h < 2; h++) {
            int s = lane + h * 32;
            float acc = -bufA[s][i];
            #pragma unroll
            for (int j = 0; j < 64; j++) acc = fmaf(__ldg(&W1[i * 64 + j]), bufA[s][j], acc);
            bufB[s][i] = acc;
        }
    }
    __syncthreads();
    #pragma unroll
    for (int it = 0; it < 8; it++) {
        int i = wid + it * 8;
        #pragma unroll
        for (int h = 0; h < 2; h++) {
            int k = lane + h * 32;
            float acc = 0.0f;
            #pragma unroll
            for (int j = 0; j < 64; j++) acc = fmaf(__ldg(&W2[i * 64 + j]), bufB[j][k], acc);
            g_h2[(size_t)n * 4096 + i * 64 + k] = fmaxf(acc, 0.0f);
        }
    }
}

// ---------------- k4b: M = We @ h2 ----------------
__global__ void __launch_bounds__(256) k4b_M(const float* __restrict__ We)
{
    int n = blockIdx.y, o0 = blockIdx.x * 64;
    __shared__ float h2s[64][65];
    int tid = threadIdx.x, wid = tid >> 5, lane = tid & 31;
    for (int e = tid; e < 4096; e += 256) h2s[e >> 6][e & 63] = g_h2[(size_t)n * 4096 + e];
    __syncthreads();
    #pragma unroll
    for (int it = 0; it < 8; it++) {
        int o = o0 + wid + it * 8;
        #pragma unroll
        for (int h = 0; h < 2; h++) {
            int t = lane + h * 32;
            float acc = 0.0f;
            #pragma unroll
            for (int j = 0; j < 64; j++) acc = fmaf(__ldg(&We[o * 64 + j]), h2s[j][t], acc);
            g_M[(size_t)n * Cc * Sn + o * 64 + t] = acc;
        }
    }
}

// ================= k5: ext band = M(128x64) @ comb-tile(64x128), exp on the fly ======
// also emits per-(channel,tile) BN partial sums.
__global__ void __launch_bounds__(256) k5_mma()
{
    extern __shared__ float smf[];
    uint32_t* smu = (uint32_t*)smf;
    const int n = blockIdx.z, band = blockIdx.y, tileX = blockIdx.x;
    const int r0 = band * 128, k0 = tileX * NT;
    const int tid = threadIdx.x, wid = tid >> 5, lane = tid & 31;
    const int wm = wid >> 2, wn = wid & 3;
    const int g = lane >> 2, t4 = lane & 3;
    const uint32_t sb = smem_u32(smf);
    float acc[4][4][4] = {};
    const float* Mb = g_M + (size_t)n * Cc * Sn;
    const float* Cb = g_t + (size_t)n * Sn * HWn + k0;

    // prefetch both A chunks via cp.async
    #pragma unroll
    for (int ch = 0; ch < 2; ch++) {
        const uint32_t base = sb + (ch ? OFF_A1 : OFF_A0) * 4;
        #pragma unroll
        for (int it = 0; it < 4; it++) {
            int idx = tid + it * 256;
            int m = idx >> 3, k4 = idx & 7;
            cp16(base + (uint32_t)(m * SA_STRIDE + k4 * 4) * 4,
                 Mb + (size_t)(r0 + m) * 64 + ch * 32 + k4 * 4);
        }
    }
    CP_COMMIT();
    // B fill (manual, exp transform)
    #pragma unroll
    for (int ch = 0; ch < 2; ch++) {
        uint32_t* uB = smu + (ch ? OFF_B1 : OFF_B0);
        #pragma unroll
        for (int it = 0; it < 4; it++) {
            int idx = tid + it * 256;
            int k = idx >> 5, n4 = idx & 31;
            int row = ch * 32 + k;
            float4 v = *(const float4*)(Cb + (size_t)row * HWn + n4 * 4);
            float Mr = __ldg(&g_rM[n * 64 + row]), Ir = __ldg(&g_rI[n * 64 + row]);
            uint4 u = {f2tf32(__expf(v.x - Mr) * Ir), f2tf32(__expf(v.y - Mr) * Ir),
                       f2tf32(__expf(v.z - Mr) * Ir), f2tf32(__expf(v.w - Mr) * Ir)};
            *(uint4*)&uB[k * SB_STRIDE + n4 * 4] = u;
        }
    }
    CP_WAIT0();
    __syncthreads();

    #pragma unroll
    for (int ch = 0; ch < 2; ch++) {
        const float* fA = smf + (ch ? OFF_A1 : OFF_A0);
        const uint32_t* uB = smu + (ch ? OFF_B1 : OFF_B0);
        #pragma unroll
        for (int ks = 0; ks < 4; ks++) {
            const int kb = ks * 8;
            uint32_t a[4][4], b[4][2];
            #pragma unroll
            for (int mt = 0; mt < 4; mt++) {
                int m = wm * 64 + mt * 16;
                a[mt][0] = f2tf32(fA[(m + g) * SA_STRIDE + kb + t4]);
                a[mt][1] = f2tf32(fA[(m + g + 8) * SA_STRIDE + kb + t4]);
                a[mt][2] = f2tf32(fA[(m + g) * SA_STRIDE + kb + t4 + 4]);
                a[mt][3] = f2tf32(fA[(m + g + 8) * SA_STRIDE + kb + t4 + 4]);
            }
            #pragma unroll
            for (int nt = 0; nt < 4; nt++) {
                int nn = wn * 32 + nt * 8;
                b[nt][0] = uB[(kb + t4) * SB_STRIDE + nn + g];
                b[nt][1] = uB[(kb + t4 + 4) * SB_STRIDE + nn + g];
            }
            #pragma unroll
            for (int mt = 0; mt < 4; mt++)
                #pragma unroll
                for (int nt = 0; nt < 4; nt++)
                    mma_tf32(acc[mt][nt], a[mt], b[nt]);
        }
    }
    __syncthreads();

    // store ext + per-row (channel) partial sums
    float* sS1 = smf;          // [4][128]
    float* sS2 = smf + 512;    // [4][128]
    const int nbase = k0 + wn * 32 + 2 * t4;
    #pragma unroll
    for (int mt = 0; mt < 4; mt++) {
        int rA = wm * 64 + mt * 16 + g;
        float* r0p = g_ext + (size_t)(n * Cc + r0 + rA) * HWn;
        float* r1p = r0p + (size_t)8 * HWn;
        float s1A = 0.f, s2A = 0.f, s1B = 0.f, s2B = 0.f;
        #pragma unroll
        for (int nt = 0; nt < 4; nt++) {
            int col = nbase + nt * 8;
            float v0 = acc[mt][nt][0], v1 = acc[mt][nt][1];
            float v2 = acc[mt][nt][2], v3 = acc[mt][nt][3];
            *(float2*)(r0p + col) = make_float2(v0, v1);
            *(float2*)(r1p + col) = make_float2(v2, v3);
            s1A += v0 + v1; s2A += v0 * v0 + v1 * v1;
            s1B += v2 + v3; s2B += v2 * v2 + v3 * v3;
        }
        s1A += __shfl_xor_sync(0xffffffffu, s1A, 1); s1A += __shfl_xor_sync(0xffffffffu, s1A, 2);
        s2A += __shfl_xor_sync(0xffffffffu, s2A, 1); s2A += __shfl_xor_sync(0xffffffffu, s2A, 2);
        s1B += __shfl_xor_sync(0xffffffffu, s1B, 1); s1B += __shfl_xor_sync(0xffffffffu, s1B, 2);
        s2B += __shfl_xor_sync(0xffffffffu, s2B, 1); s2B += __shfl_xor_sync(0xffffffffu, s2B, 2);
        if (t4 == 0) {
            sS1[wn * 128 + rA] = s1A; sS2[wn * 128 + rA] = s2A;
            sS1[wn * 128 + rA + 8] = s1B; sS2[wn * 128 + rA + 8] = s2B;
        }
    }
    __syncthreads();
    if (wn == 0 && t4 == 0) {
        #pragma unroll
        for (int mt = 0; mt < 4; mt++) {
            #pragma unroll
            for (int h = 0; h < 2; h++) {
                int r = wm * 64 + mt * 16 + g + h * 8;
                float S1 = sS1[r] + sS1[128 + r] + sS1[256 + r] + sS1[384 + r];
                float S2 = sS2[r] + sS2[128 + r] + sS2[256 + r] + sS2[384 + r];
                size_t base = ((size_t)(n * 2 + band) * NTILE + tileX) * 128 + r;
                g_ps1[base] = S1;
                g_ps2[base] = S2;
            }
        }
    }
}

// ---------------- k6r: merge BN partials -> mean / istd ----------------
__global__ void __launch_bounds__(256) k6r_stats()
{
    int c = blockIdx.x, tid = threadIdx.x;
    int band = c >> 7, row = c & 127;
    __shared__ double rs[256], rq[256];
    double s = 0.0, q = 0.0;
    for (int i = tid; i < Nn * NTILE; i += 256) {
        int n = i / NTILE, t = i % NTILE;
        size_t base = ((size_t)(n * 2 + band) * NTILE + t) * 128 + row;
        s += (double)g_ps1[base];
        q += (double)g_ps2[base];
    }
    rs[tid] = s; rq[tid] = q; __syncthreads();
    #pragma unroll
    for (int st = 128; st > 0; st >>= 1) {
        if (tid < st) { rs[tid] += rs[tid + st]; rq[tid] += rq[tid + st]; }
        __syncthreads();
    }
    if (tid == 0) {
        double cnt = (double)Nn * (double)HWn;
        double mean = rs[0] / cnt;
        double var = rq[0] / cnt - mean * mean;
        g_mean[c] = (float)mean;
        g_istd[c] = (float)rsqrt(var + 1e-5);
    }
}

// ---------------- k7: out = x + gamma*(ext-mean)*istd + beta ----------------
__global__ void __launch_bounds__(256) k7_final(const float* __restrict__ x,
                                                const float* __restrict__ gamma,
                                                const float* __restrict__ beta,
                                                float* __restrict__ out)
{
    int i = blockIdx.x * 256 + threadIdx.x;
    int c = (i / (HWn / 4)) % Cc;
    float m = g_mean[c], is = g_istd[c];
    float g = gamma[c] * is;
    float b = beta[c] - m * g;
    float4 xv = ((const float4*)x)[i];
    float4 ev = ((const float4*)g_ext)[i];
    float4 o;
    o.x = xv.x + ev.x * g + b;
    o.y = xv.y + ev.y * g + b;
    o.z = xv.z + ev.z * g + b;
    o.w = xv.w + ev.w * g + b;
    ((float4*)out)[i] = o;
}

// ---------------- launch ----------------
extern "C" void kernel_launch(void* const* d_in, const int* in_sizes, int n_in,
                              void* d_out, int out_size)
{
    const float* x     = (const float*)d_in[0];
    const float* edge  = (const float*)d_in[1];
    const float* Ws    = (const float*)d_in[2];
    const float* bs    = (const float*)d_in[3];
    const float* Wp    = (const float*)d_in[4];
    const float* bp    = (const float*)d_in[5];
    const float* W1    = (const float*)d_in[6];
    const float* W2    = (const float*)d_in[7];
    const float* We    = (const float*)d_in[8];
    const float* gamma = (const float*)d_in[9];
    const float* beta  = (const float*)d_in[10];
    float* out = (float*)d_out;

    cudaFuncSetAttribute(k1_mma, cudaFuncAttributeMaxDynamicSharedMemorySize, GEMM_SMEM_BYTES);
    cudaFuncSetAttribute(k5_mma, cudaFuncAttributeMaxDynamicSharedMemorySize, GEMM_SMEM_BYTES);

    k1_mma    <<<dim3(NTILE, Nn), 256, GEMM_SMEM_BYTES>>>(x, edge, Ws, bs, Wp, bp);
    k2s_merge <<<4, 256>>>();
    k3_mma    <<<dim3(SPLIT, Nn), 256>>>();
    k3r_reduce<<<64, 256>>>();
    k4a_gcn   <<<Nn, 256>>>(W1, W2);
    k4b_M     <<<dim3(Cc / 64, Nn), 256>>>(We);
    k5_mma    <<<dim3(NTILE, 2, Nn), 256, GEMM_SMEM_BYTES>>>();
    k6r_stats <<<Cc, 256>>>();
    k7_final  <<<(Nn * Cc * HWn / 4) / 256, 256>>>(x, gamma, beta, out);
}

// round 5
// speedup vs baseline: 2.8462x; 1.0628x over previous
#include <cuda_runtime.h>
#include <cstdint>

#define Nn   16
#define Cc   256
#define HWn  4608
#define Sn   64
#define SPLIT 12
#define KCH  (HWn / SPLIT)   // 384
#define NT   128
#define NTILE (HWn / NT)     // 36
#define CNT  ((float)Nn * (float)HWn)

// ---------------- scratch (device globals; no allocs allowed) ----------------
__device__ __align__(16) float g_xs [Nn * Sn * HWn];
__device__ __align__(16) float g_t  [Nn * Sn * HWn];          // raw gated t (pre-softmax)
__device__ __align__(16) float g_xnp[Nn * SPLIT * 128 * 64];  // [xn; G] split-K partials
__device__ __align__(16) float g_h2 [Nn * Sn * Sn];
__device__ __align__(16) float g_M  [Nn * Cc * Sn];
__device__ __align__(16) float g_pm [Nn * NTILE * Sn];        // softmax partial max
__device__ __align__(16) float g_ps [Nn * NTILE * Sn];        // softmax partial sumexp
__device__ float g_rM[Nn * Sn];                                // row max
__device__ float g_rI[Nn * Sn];                                // row 1/sum
__device__ float g_s1[Nn * Cc];                                // per-n BN sum
__device__ float g_s2[Nn * Cc];                                // per-n BN sumsq (via Gram)
__device__ float g_mean[Cc];
__device__ float g_istd[Cc];

// ---------------- helpers ----------------
__device__ __forceinline__ uint32_t smem_u32(const void* p) {
    uint32_t a;
    asm("{ .reg .u64 t; cvta.to.shared.u64 t, %1; cvt.u32.u64 %0, t; }" : "=r"(a) : "l"(p));
    return a;
}
__device__ __forceinline__ void mma_tf32(float* d, const uint32_t* a, const uint32_t* b) {
    asm volatile(
        "mma.sync.aligned.m16n8k8.row.col.f32.tf32.tf32.f32 "
        "{%0,%1,%2,%3}, {%4,%5,%6,%7}, {%8,%9}, {%0,%1,%2,%3};"
        : "+f"(d[0]), "+f"(d[1]), "+f"(d[2]), "+f"(d[3])
        : "r"(a[0]), "r"(a[1]), "r"(a[2]), "r"(a[3]), "r"(b[0]), "r"(b[1]));
}
__device__ __forceinline__ void cp16(uint32_t dst, const void* src) {
    asm volatile("cp.async.ca.shared.global [%0], [%1], 16;" :: "r"(dst), "l"(src));
}
#define CP_COMMIT()  asm volatile("cp.async.commit_group;" ::: "memory")
#define CP_WAIT0()   asm volatile("cp.async.wait_group 0;" ::: "memory")
#define CP_WAIT1()   asm volatile("cp.async.wait_group 1;" ::: "memory")
#define FU(x) __float_as_uint(x)

#define SA_STRIDE 36
#define SB_STRIDE 136
// dynamic smem float offsets
#define OFF_A0 0
#define OFF_A1 4608
#define OFF_B0 9216
#define OFF_B1 13568
#define GEMM_SMEM_BYTES (17920 * 4)   // 71680

// ================= k1: [xs;t](128 x 128cols) = [Ws;Wp](128x256) @ x-tile ============
// also emits per-(row,tile) softmax partials (max, sumexp) for the t half.
__global__ void __launch_bounds__(256) k1_mma(
    const float* __restrict__ x, const float* __restrict__ edge,
    const float* __restrict__ Ws, const float* __restrict__ bs,
    const float* __restrict__ Wp, const float* __restrict__ bp)
{
    extern __shared__ float smf[];
    const int n = blockIdx.y, tileX = blockIdx.x, k0 = tileX * NT;
    const int tid = threadIdx.x, wid = tid >> 5, lane = tid & 31;
    const int wm = wid >> 2, wn = wid & 3;
    const int g = lane >> 2, t4 = lane & 3;
    const uint32_t sb = smem_u32(smf);
    float acc[4][4][4] = {};
    const float* xb = x + (size_t)n * Cc * HWn + k0;

    auto issueA = [&](int ch, int buf) {
        const uint32_t base = sb + (buf ? OFF_A1 : OFF_A0) * 4;
        #pragma unroll
        for (int it = 0; it < 4; it++) {
            int idx = tid + it * 256;
            int m = idx >> 3, k4 = idx & 7;
            const float* src = ((m < 64) ? (Ws + m * 256) : (Wp + (m - 64) * 256))
                               + ch * 32 + k4 * 4;
            cp16(base + (uint32_t)(m * SA_STRIDE + k4 * 4) * 4, src);
        }
    };
    auto issueB = [&](int ch, int buf) {
        const uint32_t base = sb + (buf ? OFF_B1 : OFF_B0) * 4;
        #pragma unroll
        for (int it = 0; it < 4; it++) {
            int idx = tid + it * 256;
            int k = idx >> 5, n4 = idx & 31;
            cp16(base + (uint32_t)(k * SB_STRIDE + n4 * 4) * 4,
                 xb + (size_t)(ch * 32 + k) * HWn + n4 * 4);
        }
    };

    issueA(0, 0); issueB(0, 0); CP_COMMIT();

    #pragma unroll 1
    for (int ch = 0; ch < 8; ch++) {
        if (ch < 7) { issueA(ch + 1, (ch + 1) & 1); issueB(ch + 1, (ch + 1) & 1); CP_COMMIT(); CP_WAIT1(); }
        else CP_WAIT0();
        __syncthreads();
        const float* fA = smf + ((ch & 1) ? OFF_A1 : OFF_A0);
        const float* fB = smf + ((ch & 1) ? OFF_B1 : OFF_B0);
        #pragma unroll
        for (int ks = 0; ks < 4; ks++) {
            const int kb = ks * 8;
            uint32_t a[4][4], b[4][2];
            #pragma unroll
            for (int mt = 0; mt < 4; mt++) {
                int m = wm * 64 + mt * 16;
                a[mt][0] = FU(fA[(m + g) * SA_STRIDE + kb + t4]);
                a[mt][1] = FU(fA[(m + g + 8) * SA_STRIDE + kb + t4]);
                a[mt][2] = FU(fA[(m + g) * SA_STRIDE + kb + t4 + 4]);
                a[mt][3] = FU(fA[(m + g + 8) * SA_STRIDE + kb + t4 + 4]);
            }
            #pragma unroll
            for (int nt = 0; nt < 4; nt++) {
                int nn = wn * 32 + nt * 8;
                b[nt][0] = FU(fB[(kb + t4) * SB_STRIDE + nn + g]);
                b[nt][1] = FU(fB[(kb + t4 + 4) * SB_STRIDE + nn + g]);
            }
            #pragma unroll
            for (int mt = 0; mt < 4; mt++)
                #pragma unroll
                for (int nt = 0; nt < 4; nt++)
                    mma_tf32(acc[mt][nt], a[mt], b[nt]);
        }
        __syncthreads();
    }

    const int nbase = k0 + wn * 32 + 2 * t4;
    float* sPm = smf;          // [4][64]
    float* sPs = smf + 256;    // [4][64]

    if (wm == 0) {
        #pragma unroll
        for (int mt = 0; mt < 4; mt++) {
            int s0 = mt * 16 + g;
            float bv0 = bs[s0], bv1 = bs[s0 + 8];
            float* r0p = g_xs + (size_t)(n * 64 + s0) * HWn;
            float* r1p = r0p + (size_t)8 * HWn;
            #pragma unroll
            for (int nt = 0; nt < 4; nt++) {
                int col = nbase + nt * 8;
                *(float2*)(r0p + col) = make_float2(acc[mt][nt][0] + bv0, acc[mt][nt][1] + bv0);
                *(float2*)(r1p + col) = make_float2(acc[mt][nt][2] + bv1, acc[mt][nt][3] + bv1);
            }
        }
    } else {
        const float* e0p = edge + (size_t)(n * 2) * HWn;
        const float* e1p = e0p + HWn;
        float2 gate[4];
        #pragma unroll
        for (int nt = 0; nt < 4; nt++) {
            int col = nbase + nt * 8;
            float2 e0 = *(const float2*)(e0p + col);
            float2 e1 = *(const float2*)(e1p + col);
            gate[nt].x = 2.0f - 1.0f / (1.0f + __expf(e1.x - e0.x));
            gate[nt].y = 2.0f - 1.0f / (1.0f + __expf(e1.y - e0.y));
        }
        #pragma unroll
        for (int mt = 0; mt < 4; mt++) {
            int s0 = mt * 16 + g;
            float bv0 = bp[s0], bv1 = bp[s0 + 8];
            float* r0p = g_t + (size_t)(n * 64 + s0) * HWn;
            float* r1p = r0p + (size_t)8 * HWn;
            float mA = -1e30f, mB = -1e30f;
            #pragma unroll
            for (int nt = 0; nt < 4; nt++) {
                int col = nbase + nt * 8;
                float v0 = (acc[mt][nt][0] + bv0) * gate[nt].x;
                float v1 = (acc[mt][nt][1] + bv0) * gate[nt].y;
                float v2 = (acc[mt][nt][2] + bv1) * gate[nt].x;
                float v3 = (acc[mt][nt][3] + bv1) * gate[nt].y;
                acc[mt][nt][0] = v0; acc[mt][nt][1] = v1;
                acc[mt][nt][2] = v2; acc[mt][nt][3] = v3;
                *(float2*)(r0p + col) = make_float2(v0, v1);
                *(float2*)(r1p + col) = make_float2(v2, v3);
                mA = fmaxf(mA, fmaxf(v0, v1));
                mB = fmaxf(mB, fmaxf(v2, v3));
            }
            mA = fmaxf(mA, __shfl_xor_sync(0xffffffffu, mA, 1));
            mA = fmaxf(mA, __shfl_xor_sync(0xffffffffu, mA, 2));
            mB = fmaxf(mB, __shfl_xor_sync(0xffffffffu, mB, 1));
            mB = fmaxf(mB, __shfl_xor_sync(0xffffffffu, mB, 2));
            if (t4 == 0) { sPm[wn * 64 + s0] = mA; sPm[wn * 64 + s0 + 8] = mB; }
        }
    }
    __syncthreads();
    if (wm == 1) {
        #pragma unroll
        for (int mt = 0; mt < 4; mt++) {
            int rA = mt * 16 + g, rB = rA + 8;
            float MA = fmaxf(fmaxf(sPm[rA], sPm[64 + rA]), fmaxf(sPm[128 + rA], sPm[192 + rA]));
            float MB = fmaxf(fmaxf(sPm[rB], sPm[64 + rB]), fmaxf(sPm[128 + rB], sPm[192 + rB]));
            float sA = 0.f, sB = 0.f;
            #pragma unroll
            for (int nt = 0; nt < 4; nt++) {
                sA += __expf(acc[mt][nt][0] - MA) + __expf(acc[mt][nt][1] - MA);
                sB += __expf(acc[mt][nt][2] - MB) + __expf(acc[mt][nt][3] - MB);
            }
            sA += __shfl_xor_sync(0xffffffffu, sA, 1);
            sA += __shfl_xor_sync(0xffffffffu, sA, 2);
            sB += __shfl_xor_sync(0xffffffffu, sB, 1);
            sB += __shfl_xor_sync(0xffffffffu, sB, 2);
            if (t4 == 0) { sPs[wn * 64 + rA] = sA; sPs[wn * 64 + rB] = sB; }
        }
    }
    __syncthreads();
    if (wm == 1 && wn == 0 && t4 == 0) {
        #pragma unroll
        for (int mt = 0; mt < 4; mt++) {
            #pragma unroll
            for (int h = 0; h < 2; h++) {
                int r = mt * 16 + g + h * 8;
                float M = fmaxf(fmaxf(sPm[r], sPm[64 + r]), fmaxf(sPm[128 + r], sPm[192 + r]));
                float S = sPs[r] + sPs[64 + r] + sPs[128 + r] + sPs[192 + r];
                g_pm[(size_t)(n * NTILE + tileX) * 64 + r] = M;
                g_ps[(size_t)(n * NTILE + tileX) * 64 + r] = S;
            }
        }
    }
}

// ---------------- k2s: merge softmax partials -> row max, row 1/sum ----------------
__global__ void __launch_bounds__(256) k2s_merge()
{
    int idx = blockIdx.x * 256 + threadIdx.x;     // 1024 rows
    int n = idx >> 6, s = idx & 63;
    float M = -1e30f;
    #pragma unroll
    for (int t = 0; t < NTILE; t++)
        M = fmaxf(M, g_pm[(size_t)(n * NTILE + t) * 64 + s]);
    float S = 0.f;
    #pragma unroll
    for (int t = 0; t < NTILE; t++)
        S += g_ps[(size_t)(n * NTILE + t) * 64 + s] *
             __expf(g_pm[(size_t)(n * NTILE + t) * 64 + s] - M);
    g_rM[idx] = M;
    g_rI[idx] = 1.0f / S;
}

// ================= k3g: [xn; G] = [xs; comb](128xK) @ comb(64xK)^T, split-K ==========
__global__ void __launch_bounds__(256) k3g_mma()
{
    __shared__ float sA[64 * SA_STRIDE];   // xs   [m][k]
    __shared__ float sB[64 * SA_STRIDE];   // comb [n][k] (also A rows 64-127)
    const int sp = blockIdx.x, n = blockIdx.y;
    const int koff = sp * KCH;
    const int tid = threadIdx.x, wid = tid >> 5, lane = tid & 31;
    const int wm = wid >> 1, wn = wid & 1;      // 4 x 2 warps
    const int g = lane >> 2, t4 = lane & 3;
    float acc[2][4][4] = {};
    const float* A = g_xs + (size_t)n * Sn * HWn + koff;
    const float* B = g_t  + (size_t)n * Sn * HWn + koff;
    const float* srcA = (wm < 2) ? sA : sB;
    const int mloc = (wm & 1) * 32;

    #pragma unroll 1
    for (int ch = 0; ch < KCH / 32; ch++) {
        const int c0 = ch * 32;
        #pragma unroll
        for (int it = 0; it < 2; it++) {
            int idx = tid + it * 256;
            int m = idx >> 3, k4 = idx & 7;
            float4 va = *(const float4*)(A + (size_t)m * HWn + c0 + k4 * 4);
            float4 vb = *(const float4*)(B + (size_t)m * HWn + c0 + k4 * 4);
            float Mr = __ldg(&g_rM[n * 64 + m]), Ir = __ldg(&g_rI[n * 64 + m]);
            vb.x = __expf(vb.x - Mr) * Ir; vb.y = __expf(vb.y - Mr) * Ir;
            vb.z = __expf(vb.z - Mr) * Ir; vb.w = __expf(vb.w - Mr) * Ir;
            *(float4*)&sA[m * SA_STRIDE + k4 * 4] = va;
            *(float4*)&sB[m * SA_STRIDE + k4 * 4] = vb;
        }
        __syncthreads();
        #pragma unroll
        for (int ks = 0; ks < 4; ks++) {
            const int kb = ks * 8;
            uint32_t a[2][4], b[4][2];
            #pragma unroll
            for (int mt = 0; mt < 2; mt++) {
                int m = mloc + mt * 16;
                a[mt][0] = FU(srcA[(m + g) * SA_STRIDE + kb + t4]);
                a[mt][1] = FU(srcA[(m + g + 8) * SA_STRIDE + kb + t4]);
                a[mt][2] = FU(srcA[(m + g) * SA_STRIDE + kb + t4 + 4]);
                a[mt][3] = FU(srcA[(m + g + 8) * SA_STRIDE + kb + t4 + 4]);
            }
            #pragma unroll
            for (int nt = 0; nt < 4; nt++) {
                int nn = wn * 32 + nt * 8;
                b[nt][0] = FU(sB[(nn + g) * SA_STRIDE + kb + t4]);
                b[nt][1] = FU(sB[(nn + g) * SA_STRIDE + kb + t4 + 4]);
            }
            #pragma unroll
            for (int mt = 0; mt < 2; mt++)
                #pragma unroll
                for (int nt = 0; nt < 4; nt++)
                    mma_tf32(acc[mt][nt], a[mt], b[nt]);
        }
        __syncthreads();
    }

    float* dst = g_xnp + (size_t)(n * SPLIT + sp) * 8192;
    #pragma unroll
    for (int mt = 0; mt < 2; mt++) {
        int r = wm * 32 + mt * 16 + g;
        #pragma unroll
        for (int nt = 0; nt < 4; nt++) {
            int t = wn * 32 + nt * 8 + 2 * t4;
            *(float2*)(dst + r * 64 + t)       = make_float2(acc[mt][nt][0], acc[mt][nt][1]);
            *(float2*)(dst + (r + 8) * 64 + t) = make_float2(acc[mt][nt][2], acc[mt][nt][3]);
        }
    }
}

// ---------------- k4a: reduce xn partials + GCN -> h2 ----------------
__global__ void __launch_bounds__(256) k4a_gcn(const float* __restrict__ W1,
                                               const float* __restrict__ W2)
{
    int n = blockIdx.x;
    __shared__ float bufA[64][65];
    __shared__ float bufB[64][65];
    int tid = threadIdx.x, wid = tid >> 5, lane = tid & 31;

    for (int e = tid; e < 4096; e += 256) {
        float s = 0.f;
        #pragma unroll
        for (int p = 0; p < SPLIT; p++)
            s += g_xnp[(size_t)(n * SPLIT + p) * 8192 + e];
        bufA[e >> 6][e & 63] = s;
    }
    __syncthreads();
    #pragma unroll
    for (int it = 0; it < 8; it++) {
        int i = wid + it * 8;
        #pragma unroll
        for (int h = 0; h < 2; h++) {
            int s = lane + h * 32;
            float acc = -bufA[s][i];
            #pragma unroll
            for (int j = 0; j < 64; j++) acc = fmaf(__ldg(&W1[i * 64 + j]), bufA[s][j], acc);
            bufB[s][i] = acc;
        }
    }
    __syncthreads();
    #pragma unroll
    for (int it = 0; it < 8; it++) {
        int i = wid + it * 8;
        #pragma unroll
        for (int h = 0; h < 2; h++) {
            int k = lane + h * 32;
            float acc = 0.0f;
            #pragma unroll
            for (int j = 0; j < 64; j++) acc = fmaf(__ldg(&W2[i * 64 + j]), bufB[j][k], acc);
            g_h2[(size_t)n * 4096 + i * 64 + k] = fmaxf(acc, 0.0f);
        }
    }
}

// ---------------- k4b: M = We @ h2 ----------------
__global__ void __launch_bounds__(256) k4b_M(const float* __restrict__ We)
{
    int n = blockIdx.y, o0 = blockIdx.x * 64;
    __shared__ float h2s[64][65];
    int tid = threadIdx.x, wid = tid >> 5, lane = tid & 31;
    for (int e = tid; e < 4096; e += 256) h2s[e >> 6][e & 63] = g_h2[(size_t)n * 4096 + e];
    __syncthreads();
    #pragma unroll
    for (int it = 0; it < 8; it++) {
        int o = o0 + wid + it * 8;
        #pragma unroll
        for (int h = 0; h < 2; h++) {
            int t = lane + h * 32;
            float acc = 0.0f;
            #pragma unroll
            for (int j = 0; j < 64; j++) acc = fmaf(__ldg(&We[o * 64 + j]), h2s[j][t], acc);
            g_M[(size_t)n * Cc * Sn + o * 64 + t] = acc;
        }
    }
}

// ---------------- k4c: per-(n,c) BN partials from Gram: s1 = Σ m, s2 = m G m^T ------
__global__ void __launch_bounds__(256) k4c_stat()
{
    int n = blockIdx.x, tid = threadIdx.x;
    __shared__ float sG[64][68];
    for (int e = tid; e < 4096; e += 256) {
        float s = 0.f;
        #pragma unroll
        for (int p = 0; p < SPLIT; p++)
            s += g_xnp[(size_t)(n * SPLIT + p) * 8192 + 4096 + e];
        sG[e >> 6][e & 63] = s;
    }
    __syncthreads();

    const int c = tid;
    float m[64];
    const float4* mp = (const float4*)(g_M + (size_t)n * Cc * Sn + c * 64);
    #pragma unroll
    for (int t4i = 0; t4i < 16; t4i++) {
        float4 v = mp[t4i];
        m[t4i * 4] = v.x; m[t4i * 4 + 1] = v.y; m[t4i * 4 + 2] = v.z; m[t4i * 4 + 3] = v.w;
    }
    float s1 = 0.f;
    #pragma unroll
    for (int t = 0; t < 64; t++) s1 += m[t];
    float q = 0.f;
    #pragma unroll 4
    for (int t = 0; t < 64; t++) {
        float w = 0.f;
        #pragma unroll
        for (int u4 = 0; u4 < 16; u4++) {
            float4 gv = *(const float4*)&sG[t][u4 * 4];
            w += gv.x * m[u4 * 4] + gv.y * m[u4 * 4 + 1]
               + gv.z * m[u4 * 4 + 2] + gv.w * m[u4 * 4 + 3];
        }
        q = fmaf(m[t], w, q);
    }
    g_s1[n * Cc + c] = s1;
    g_s2[n * Cc + c] = q;
}

// ---------------- k6r: merge BN partials -> mean / istd ----------------
__global__ void __launch_bounds__(256) k6r_stats()
{
    int c = threadIdx.x;
    float s = 0.f, q = 0.f;
    #pragma unroll
    for (int n = 0; n < Nn; n++) { s += g_s1[n * Cc + c]; q += g_s2[n * Cc + c]; }
    float mean = s / CNT;
    float var = q / CNT - mean * mean;
    g_mean[c] = mean;
    g_istd[c] = rsqrtf(var + 1e-5f);
}

// ================= k7g: out = x + BN(M(128x64) @ comb-tile(64x128)) ==================
__global__ void __launch_bounds__(256) k7g_mma(
    const float* __restrict__ x, const float* __restrict__ gamma,
    const float* __restrict__ beta, float* __restrict__ out)
{
    extern __shared__ float smf[];
    uint32_t* smu = (uint32_t*)smf;
    const int n = blockIdx.z, band = blockIdx.y, tileX = blockIdx.x;
    const int r0 = band * 128, k0 = tileX * NT;
    const int tid = threadIdx.x, wid = tid >> 5, lane = tid & 31;
    const int wm = wid >> 2, wn = wid & 3;
    const int g = lane >> 2, t4 = lane & 3;
    const uint32_t sb = smem_u32(smf);
    float acc[4][4][4] = {};
    const float* Mb = g_M + (size_t)n * Cc * Sn;
    const float* Cb = g_t + (size_t)n * Sn * HWn + k0;

    #pragma unroll
    for (int ch = 0; ch < 2; ch++) {
        const uint32_t base = sb + (ch ? OFF_A1 : OFF_A0) * 4;
        #pragma unroll
        for (int it = 0; it < 4; it++) {
            int idx = tid + it * 256;
            int m = idx >> 3, k4 = idx & 7;
            cp16(base + (uint32_t)(m * SA_STRIDE + k4 * 4) * 4,
                 Mb + (size_t)(r0 + m) * 64 + ch * 32 + k4 * 4);
        }
    }
    CP_COMMIT();
    #pragma unroll
    for (int ch = 0; ch < 2; ch++) {
        uint32_t* uB = smu + (ch ? OFF_B1 : OFF_B0);
        #pragma unroll
        for (int it = 0; it < 4; it++) {
            int idx = tid + it * 256;
            int k = idx >> 5, n4 = idx & 31;
            int row = ch * 32 + k;
            float4 v = *(const float4*)(Cb + (size_t)row * HWn + n4 * 4);
            float Mr = __ldg(&g_rM[n * 64 + row]), Ir = __ldg(&g_rI[n * 64 + row]);
            uint4 u = {FU(__expf(v.x - Mr) * Ir), FU(__expf(v.y - Mr) * Ir),
                       FU(__expf(v.z - Mr) * Ir), FU(__expf(v.w - Mr) * Ir)};
            *(uint4*)&uB[k * SB_STRIDE + n4 * 4] = u;
        }
    }
    CP_WAIT0();
    __syncthreads();

    #pragma unroll
    for (int ch = 0; ch < 2; ch++) {
        const float* fA = smf + (ch ? OFF_A1 : OFF_A0);
        const uint32_t* uB = smu + (ch ? OFF_B1 : OFF_B0);
        #pragma unroll
        for (int ks = 0; ks < 4; ks++) {
            const int kb = ks * 8;
            uint32_t a[4][4], b[4][2];
            #pragma unroll
            for (int mt = 0; mt < 4; mt++) {
                int m = wm * 64 + mt * 16;
                a[mt][0] = FU(fA[(m + g) * SA_STRIDE + kb + t4]);
                a[mt][1] = FU(fA[(m + g + 8) * SA_STRIDE + kb + t4]);
                a[mt][2] = FU(fA[(m + g) * SA_STRIDE + kb + t4 + 4]);
                a[mt][3] = FU(fA[(m + g + 8) * SA_STRIDE + kb + t4 + 4]);
            }
            #pragma unroll
            for (int nt = 0; nt < 4; nt++) {
                int nn = wn * 32 + nt * 8;
                b[nt][0] = uB[(kb + t4) * SB_STRIDE + nn + g];
                b[nt][1] = uB[(kb + t4 + 4) * SB_STRIDE + nn + g];
            }
            #pragma unroll
            for (int mt = 0; mt < 4; mt++)
                #pragma unroll
                for (int nt = 0; nt < 4; nt++)
                    mma_tf32(acc[mt][nt], a[mt], b[nt]);
        }
    }

    // epilogue: out = x + gamma*(v-mean)*istd + beta
    const int nbase = k0 + wn * 32 + 2 * t4;
    #pragma unroll
    for (int mt = 0; mt < 4; mt++) {
        int cA = r0 + wm * 64 + mt * 16 + g;
        int cB = cA + 8;
        float gA = gamma[cA] * g_istd[cA], bA = beta[cA] - g_mean[cA] * gA;
        float gB = gamma[cB] * g_istd[cB], bB = beta[cB] - g_mean[cB] * gB;
        const float* x0p = x + (size_t)(n * Cc + cA) * HWn;
        const float* x1p = x0p + (size_t)8 * HWn;
        float* o0p = out + (size_t)(n * Cc + cA) * HWn;
        float* o1p = o0p + (size_t)8 * HWn;
        #pragma unroll
        for (int nt = 0; nt < 4; nt++) {
            int col = nbase + nt * 8;
            float2 xv0 = *(const float2*)(x0p + col);
            float2 xv1 = *(const float2*)(x1p + col);
            *(float2*)(o0p + col) = make_float2(xv0.x + acc[mt][nt][0] * gA + bA,
                                                xv0.y + acc[mt][nt][1] * gA + bA);
            *(float2*)(o1p + col) = make_float2(xv1.x + acc[mt][nt][2] * gB + bB,
                                                xv1.y + acc[mt][nt][3] * gB + bB);
        }
    }
}

// ---------------- launch ----------------
extern "C" void kernel_launch(void* const* d_in, const int* in_sizes, int n_in,
                              void* d_out, int out_size)
{
    const float* x     = (const float*)d_in[0];
    const float* edge  = (const float*)d_in[1];
    const float* Ws    = (const float*)d_in[2];
    const float* bs    = (const float*)d_in[3];
    const float* Wp    = (const float*)d_in[4];
    const float* bp    = (const float*)d_in[5];
    const float* W1    = (const float*)d_in[6];
    const float* W2    = (const float*)d_in[7];
    const float* We    = (const float*)d_in[8];
    const float* gamma = (const float*)d_in[9];
    const float* beta  = (const float*)d_in[10];
    float* out = (float*)d_out;

    cudaFuncSetAttribute(k1_mma, cudaFuncAttributeMaxDynamicSharedMemorySize, GEMM_SMEM_BYTES);
    cudaFuncSetAttribute(k7g_mma, cudaFuncAttributeMaxDynamicSharedMemorySize, GEMM_SMEM_BYTES);

    k1_mma    <<<dim3(NTILE, Nn), 256, GEMM_SMEM_BYTES>>>(x, edge, Ws, bs, Wp, bp);
    k2s_merge <<<4, 256>>>();
    k3g_mma   <<<dim3(SPLIT, Nn), 256>>>();
    k4a_gcn   <<<Nn, 256>>>(W1, W2);
    k4b_M     <<<dim3(Cc / 64, Nn), 256>>>(We);
    k4c_stat  <<<Nn, 256>>>();
    k6r_stats <<<1, 256>>>();
    k7g_mma   <<<dim3(NTILE, 2, Nn), 256, GEMM_SMEM_BYTES>>>(x, gamma, beta, out);
}

// round 6
// speedup vs baseline: 3.6749x; 1.2911x over previous
#include <cuda_runtime.h>
#include <cstdint>

#define Nn   16
#define Cc   256
#define HWn  4608
#define Sn   64
#define SPLIT 12
#define KCH  (HWn / SPLIT)   // 384
#define NT   128
#define NTILE (HWn / NT)     // 36
#define CNT  ((float)Nn * (float)HWn)

// ---------------- scratch (device globals; no allocs allowed) ----------------
__device__ __align__(16) float g_xs [Nn * Sn * HWn];
__device__ __align__(16) float g_t  [Nn * Sn * HWn];          // raw gated t (pre-softmax)
__device__ __align__(16) float g_xnp[Nn * SPLIT * 128 * 64];  // [xn; G] split-K partials
__device__ __align__(16) float g_M  [Nn * Cc * Sn];
__device__ __align__(16) float g_pm [Nn * NTILE * Sn];        // softmax partial max
__device__ __align__(16) float g_ps [Nn * NTILE * Sn];        // softmax partial sumexp
__device__ float g_rM[Nn * Sn];                                // row max
__device__ float g_rI[Nn * Sn];                                // row 1/sum
__device__ float g_s1[Nn * Cc];                                // per-n BN sum
__device__ float g_s2[Nn * Cc];                                // per-n BN sumsq

// ---------------- helpers ----------------
__device__ __forceinline__ uint32_t smem_u32(const void* p) {
    uint32_t a;
    asm("{ .reg .u64 t; cvta.to.shared.u64 t, %1; cvt.u32.u64 %0, t; }" : "=r"(a) : "l"(p));
    return a;
}
__device__ __forceinline__ void mma_tf32(float* d, const uint32_t* a, const uint32_t* b) {
    asm volatile(
        "mma.sync.aligned.m16n8k8.row.col.f32.tf32.tf32.f32 "
        "{%0,%1,%2,%3}, {%4,%5,%6,%7}, {%8,%9}, {%0,%1,%2,%3};"
        : "+f"(d[0]), "+f"(d[1]), "+f"(d[2]), "+f"(d[3])
        : "r"(a[0]), "r"(a[1]), "r"(a[2]), "r"(a[3]), "r"(b[0]), "r"(b[1]));
}
__device__ __forceinline__ void cp16(uint32_t dst, const void* src) {
    asm volatile("cp.async.ca.shared.global [%0], [%1], 16;" :: "r"(dst), "l"(src));
}
#define CP_COMMIT()  asm volatile("cp.async.commit_group;" ::: "memory")
#define CP_WAIT0()   asm volatile("cp.async.wait_group 0;" ::: "memory")
#define CP_WAIT1()   asm volatile("cp.async.wait_group 1;" ::: "memory")
#define FU(x) __float_as_uint(x)

#define SA_STRIDE 36
#define SB_STRIDE 136
// dynamic smem float offsets (GEMM kernels)
#define OFF_A0 0
#define OFF_A1 4608
#define OFF_B0 9216
#define OFF_B1 13568
#define GEMM_SMEM_FLOATS 17920
#define K1_SMEM_BYTES (GEMM_SMEM_FLOATS * 4)
#define K7_SMEM_BYTES ((GEMM_SMEM_FLOATS + 256) * 4)

// ================= k1: [xs;t](128 x 128cols) = [Ws;Wp](128x256) @ x-tile ============
__global__ void __launch_bounds__(256) k1_mma(
    const float* __restrict__ x, const float* __restrict__ edge,
    const float* __restrict__ Ws, const float* __restrict__ bs,
    const float* __restrict__ Wp, const float* __restrict__ bp)
{
    extern __shared__ float smf[];
    const int n = blockIdx.y, tileX = blockIdx.x, k0 = tileX * NT;
    const int tid = threadIdx.x, wid = tid >> 5, lane = tid & 31;
    const int wm = wid >> 2, wn = wid & 3;
    const int g = lane >> 2, t4 = lane & 3;
    const uint32_t sb = smem_u32(smf);
    float acc[4][4][4] = {};
    const float* xb = x + (size_t)n * Cc * HWn + k0;

    auto issueA = [&](int ch, int buf) {
        const uint32_t base = sb + (buf ? OFF_A1 : OFF_A0) * 4;
        #pragma unroll
        for (int it = 0; it < 4; it++) {
            int idx = tid + it * 256;
            int m = idx >> 3, k4 = idx & 7;
            const float* src = ((m < 64) ? (Ws + m * 256) : (Wp + (m - 64) * 256))
                               + ch * 32 + k4 * 4;
            cp16(base + (uint32_t)(m * SA_STRIDE + k4 * 4) * 4, src);
        }
    };
    auto issueB = [&](int ch, int buf) {
        const uint32_t base = sb + (buf ? OFF_B1 : OFF_B0) * 4;
        #pragma unroll
        for (int it = 0; it < 4; it++) {
            int idx = tid + it * 256;
            int k = idx >> 5, n4 = idx & 31;
            cp16(base + (uint32_t)(k * SB_STRIDE + n4 * 4) * 4,
                 xb + (size_t)(ch * 32 + k) * HWn + n4 * 4);
        }
    };

    issueA(0, 0); issueB(0, 0); CP_COMMIT();

    #pragma unroll 1
    for (int ch = 0; ch < 8; ch++) {
        if (ch < 7) { issueA(ch + 1, (ch + 1) & 1); issueB(ch + 1, (ch + 1) & 1); CP_COMMIT(); CP_WAIT1(); }
        else CP_WAIT0();
        __syncthreads();
        const float* fA = smf + ((ch & 1) ? OFF_A1 : OFF_A0);
        const float* fB = smf + ((ch & 1) ? OFF_B1 : OFF_B0);
        #pragma unroll
        for (int ks = 0; ks < 4; ks++) {
            const int kb = ks * 8;
            uint32_t a[4][4], b[4][2];
            #pragma unroll
            for (int mt = 0; mt < 4; mt++) {
                int m = wm * 64 + mt * 16;
                a[mt][0] = FU(fA[(m + g) * SA_STRIDE + kb + t4]);
                a[mt][1] = FU(fA[(m + g + 8) * SA_STRIDE + kb + t4]);
                a[mt][2] = FU(fA[(m + g) * SA_STRIDE + kb + t4 + 4]);
                a[mt][3] = FU(fA[(m + g + 8) * SA_STRIDE + kb + t4 + 4]);
            }
            #pragma unroll
            for (int nt = 0; nt < 4; nt++) {
                int nn = wn * 32 + nt * 8;
                b[nt][0] = FU(fB[(kb + t4) * SB_STRIDE + nn + g]);
                b[nt][1] = FU(fB[(kb + t4 + 4) * SB_STRIDE + nn + g]);
            }
            #pragma unroll
            for (int mt = 0; mt < 4; mt++)
                #pragma unroll
                for (int nt = 0; nt < 4; nt++)
                    mma_tf32(acc[mt][nt], a[mt], b[nt]);
        }
        __syncthreads();
    }

    const int nbase = k0 + wn * 32 + 2 * t4;
    float* sPm = smf;          // [4][64]
    float* sPs = smf + 256;    // [4][64]

    if (wm == 0) {
        #pragma unroll
        for (int mt = 0; mt < 4; mt++) {
            int s0 = mt * 16 + g;
            float bv0 = bs[s0], bv1 = bs[s0 + 8];
            float* r0p = g_xs + (size_t)(n * 64 + s0) * HWn;
            float* r1p = r0p + (size_t)8 * HWn;
            #pragma unroll
            for (int nt = 0; nt < 4; nt++) {
                int col = nbase + nt * 8;
                *(float2*)(r0p + col) = make_float2(acc[mt][nt][0] + bv0, acc[mt][nt][1] + bv0);
                *(float2*)(r1p + col) = make_float2(acc[mt][nt][2] + bv1, acc[mt][nt][3] + bv1);
            }
        }
    } else {
        const float* e0p = edge + (size_t)(n * 2) * HWn;
        const float* e1p = e0p + HWn;
        float2 gate[4];
        #pragma unroll
        for (int nt = 0; nt < 4; nt++) {
            int col = nbase + nt * 8;
            float2 e0 = *(const float2*)(e0p + col);
            float2 e1 = *(const float2*)(e1p + col);
            gate[nt].x = 2.0f - 1.0f / (1.0f + __expf(e1.x - e0.x));
            gate[nt].y = 2.0f - 1.0f / (1.0f + __expf(e1.y - e0.y));
        }
        #pragma unroll
        for (int mt = 0; mt < 4; mt++) {
            int s0 = mt * 16 + g;
            float bv0 = bp[s0], bv1 = bp[s0 + 8];
            float* r0p = g_t + (size_t)(n * 64 + s0) * HWn;
            float* r1p = r0p + (size_t)8 * HWn;
            float mA = -1e30f, mB = -1e30f;
            #pragma unroll
            for (int nt = 0; nt < 4; nt++) {
                int col = nbase + nt * 8;
                float v0 = (acc[mt][nt][0] + bv0) * gate[nt].x;
                float v1 = (acc[mt][nt][1] + bv0) * gate[nt].y;
                float v2 = (acc[mt][nt][2] + bv1) * gate[nt].x;
                float v3 = (acc[mt][nt][3] + bv1) * gate[nt].y;
                acc[mt][nt][0] = v0; acc[mt][nt][1] = v1;
                acc[mt][nt][2] = v2; acc[mt][nt][3] = v3;
                *(float2*)(r0p + col) = make_float2(v0, v1);
                *(float2*)(r1p + col) = make_float2(v2, v3);
                mA = fmaxf(mA, fmaxf(v0, v1));
                mB = fmaxf(mB, fmaxf(v2, v3));
            }
            mA = fmaxf(mA, __shfl_xor_sync(0xffffffffu, mA, 1));
            mA = fmaxf(mA, __shfl_xor_sync(0xffffffffu, mA, 2));
            mB = fmaxf(mB, __shfl_xor_sync(0xffffffffu, mB, 1));
            mB = fmaxf(mB, __shfl_xor_sync(0xffffffffu, mB, 2));
            if (t4 == 0) { sPm[wn * 64 + s0] = mA; sPm[wn * 64 + s0 + 8] = mB; }
        }
    }
    __syncthreads();
    if (wm == 1) {
        #pragma unroll
        for (int mt = 0; mt < 4; mt++) {
            int rA = mt * 16 + g, rB = rA + 8;
            float MA = fmaxf(fmaxf(sPm[rA], sPm[64 + rA]), fmaxf(sPm[128 + rA], sPm[192 + rA]));
            float MB = fmaxf(fmaxf(sPm[rB], sPm[64 + rB]), fmaxf(sPm[128 + rB], sPm[192 + rB]));
            float sA = 0.f, sB = 0.f;
            #pragma unroll
            for (int nt = 0; nt < 4; nt++) {
                sA += __expf(acc[mt][nt][0] - MA) + __expf(acc[mt][nt][1] - MA);
                sB += __expf(acc[mt][nt][2] - MB) + __expf(acc[mt][nt][3] - MB);
            }
            sA += __shfl_xor_sync(0xffffffffu, sA, 1);
            sA += __shfl_xor_sync(0xffffffffu, sA, 2);
            sB += __shfl_xor_sync(0xffffffffu, sB, 1);
            sB += __shfl_xor_sync(0xffffffffu, sB, 2);
            if (t4 == 0) { sPs[wn * 64 + rA] = sA; sPs[wn * 64 + rB] = sB; }
        }
    }
    __syncthreads();
    if (wm == 1 && wn == 0 && t4 == 0) {
        #pragma unroll
        for (int mt = 0; mt < 4; mt++) {
            #pragma unroll
            for (int h = 0; h < 2; h++) {
                int r = mt * 16 + g + h * 8;
                float M = fmaxf(fmaxf(sPm[r], sPm[64 + r]), fmaxf(sPm[128 + r], sPm[192 + r]));
                float S = sPs[r] + sPs[64 + r] + sPs[128 + r] + sPs[192 + r];
                g_pm[(size_t)(n * NTILE + tileX) * 64 + r] = M;
                g_ps[(size_t)(n * NTILE + tileX) * 64 + r] = S;
            }
        }
    }
}

// ================= k3g: [xn; G] = [xs; comb](128xK) @ comb(64xK)^T, split-K ==========
// computes row softmax stats in-block (folds old k2s); block sp==0 publishes them.
__global__ void __launch_bounds__(256) k3g_mma()
{
    __shared__ float sA[64 * SA_STRIDE];
    __shared__ float sB[64 * SA_STRIDE];
    __shared__ float sPm4[4][64], sPs4[4][64];
    __shared__ float sRm[64], sRi[64];
    const int sp = blockIdx.x, n = blockIdx.y;
    const int koff = sp * KCH;
    const int tid = threadIdx.x, wid = tid >> 5, lane = tid & 31;
    const int wm = wid >> 1, wn = wid & 1;      // 4 x 2 warps
    const int g = lane >> 2, t4 = lane & 3;

    // ---- softmax stats (redundant per block; cheap, L2-hot) ----
    {
        int s = tid & 63, part = tid >> 6;
        float mt9[9];
        float Mp = -1e30f;
        #pragma unroll
        for (int t = 0; t < 9; t++) {
            mt9[t] = g_pm[(size_t)(n * NTILE + part * 9 + t) * 64 + s];
            Mp = fmaxf(Mp, mt9[t]);
        }
        float Sp = 0.f;
        #pragma unroll
        for (int t = 0; t < 9; t++)
            Sp += g_ps[(size_t)(n * NTILE + part * 9 + t) * 64 + s] * __expf(mt9[t] - Mp);
        sPm4[part][s] = Mp; sPs4[part][s] = Sp;
    }
    __syncthreads();
    if (tid < 64) {
        float M = fmaxf(fmaxf(sPm4[0][tid], sPm4[1][tid]), fmaxf(sPm4[2][tid], sPm4[3][tid]));
        float S = sPs4[0][tid] * __expf(sPm4[0][tid] - M) + sPs4[1][tid] * __expf(sPm4[1][tid] - M)
                + sPs4[2][tid] * __expf(sPm4[2][tid] - M) + sPs4[3][tid] * __expf(sPm4[3][tid] - M);
        sRm[tid] = M;
        sRi[tid] = 1.0f / S;
        if (sp == 0) { g_rM[n * 64 + tid] = M; g_rI[n * 64 + tid] = 1.0f / S; }
    }
    __syncthreads();

    float acc[2][4][4] = {};
    const float* A = g_xs + (size_t)n * Sn * HWn + koff;
    const float* B = g_t  + (size_t)n * Sn * HWn + koff;
    const float* srcA = (wm < 2) ? sA : sB;
    const int mloc = (wm & 1) * 32;

    #pragma unroll 1
    for (int ch = 0; ch < KCH / 32; ch++) {
        const int c0 = ch * 32;
        #pragma unroll
        for (int it = 0; it < 2; it++) {
            int idx = tid + it * 256;
            int m = idx >> 3, k4 = idx & 7;
            float4 va = *(const float4*)(A + (size_t)m * HWn + c0 + k4 * 4);
            float4 vb = *(const float4*)(B + (size_t)m * HWn + c0 + k4 * 4);
            float Mr = sRm[m], Ir = sRi[m];
            vb.x = __expf(vb.x - Mr) * Ir; vb.y = __expf(vb.y - Mr) * Ir;
            vb.z = __expf(vb.z - Mr) * Ir; vb.w = __expf(vb.w - Mr) * Ir;
            *(float4*)&sA[m * SA_STRIDE + k4 * 4] = va;
            *(float4*)&sB[m * SA_STRIDE + k4 * 4] = vb;
        }
        __syncthreads();
        #pragma unroll
        for (int ks = 0; ks < 4; ks++) {
            const int kb = ks * 8;
            uint32_t a[2][4], b[4][2];
            #pragma unroll
            for (int mt = 0; mt < 2; mt++) {
                int m = mloc + mt * 16;
                a[mt][0] = FU(srcA[(m + g) * SA_STRIDE + kb + t4]);
                a[mt][1] = FU(srcA[(m + g + 8) * SA_STRIDE + kb + t4]);
                a[mt][2] = FU(srcA[(m + g) * SA_STRIDE + kb + t4 + 4]);
                a[mt][3] = FU(srcA[(m + g + 8) * SA_STRIDE + kb + t4 + 4]);
            }
            #pragma unroll
            for (int nt = 0; nt < 4; nt++) {
                int nn = wn * 32 + nt * 8;
                b[nt][0] = FU(sB[(nn + g) * SA_STRIDE + kb + t4]);
                b[nt][1] = FU(sB[(nn + g) * SA_STRIDE + kb + t4 + 4]);
            }
            #pragma unroll
            for (int mt = 0; mt < 2; mt++)
                #pragma unroll
                for (int nt = 0; nt < 4; nt++)
                    mma_tf32(acc[mt][nt], a[mt], b[nt]);
        }
        __syncthreads();
    }

    float* dst = g_xnp + (size_t)(n * SPLIT + sp) * 8192;
    #pragma unroll
    for (int mt = 0; mt < 2; mt++) {
        int r = wm * 32 + mt * 16 + g;
        #pragma unroll
        for (int nt = 0; nt < 4; nt++) {
            int t = wn * 32 + nt * 8 + 2 * t4;
            *(float2*)(dst + r * 64 + t)       = make_float2(acc[mt][nt][0], acc[mt][nt][1]);
            *(float2*)(dst + (r + 8) * 64 + t) = make_float2(acc[mt][nt][2], acc[mt][nt][3]);
        }
    }
}

// ================= k4f: fused GCN + M + BN partials (all tensor-pipe) ================
// per block (one per n): reduce [xn;G] partials; h1 = xn@W1^T - xn; h2 = relu(W2@h1);
// M = We@h2 (stored); R = M@G; s1 = rowsum(M); s2 = rowdot(M,R).
#define S68 68
#define K4F_SMEM ((3 * 64 * S68 + 128 * S68) * 4)   // 87040 B
__global__ void __launch_bounds__(256) k4f(
    const float* __restrict__ W1, const float* __restrict__ W2,
    const float* __restrict__ We)
{
    extern __shared__ float sm[];
    float* sXn = sm;                  // xn, later h2 [i][k]
    float* sG  = sm + 64 * S68;       // G [t][u]
    float* sHT = sm + 2 * 64 * S68;   // h1 transposed: sHT[i][s] = h1[s][i]
    float* sMb = sm + 3 * 64 * S68;   // M band [128][68]
    const int n = blockIdx.x;
    const int tid = threadIdx.x, wid = tid >> 5, lane = tid & 31;
    const int g = lane >> 2, t4 = lane & 3;

    // ---- reduce split-K partials ----
    #pragma unroll
    for (int it = 0; it < 4; it++) {
        int idx = tid + it * 256;              // 1024 float4 per matrix
        int row = idx >> 4, col = (idx & 15) * 4;
        float4 sx = {0.f,0.f,0.f,0.f}, sg = {0.f,0.f,0.f,0.f};
        #pragma unroll
        for (int p = 0; p < SPLIT; p++) {
            const float* base = g_xnp + (size_t)(n * SPLIT + p) * 8192;
            float4 a = *(const float4*)(base + row * 64 + col);
            float4 b = *(const float4*)(base + 4096 + row * 64 + col);
            sx.x += a.x; sx.y += a.y; sx.z += a.z; sx.w += a.w;
            sg.x += b.x; sg.y += b.y; sg.z += b.z; sg.w += b.w;
        }
        *(float4*)&sXn[row * S68 + col] = sx;
        *(float4*)&sG [row * S68 + col] = sg;
    }
    __syncthreads();

    // ---- phase 1: h1 = xn @ W1^T - xn (64x64), store transposed ----
    {
        const int wm = wid >> 2, wn = wid & 3;   // 2 x 4
        float hacc[2][2][4] = {};
        #pragma unroll
        for (int ks = 0; ks < 8; ks++) {
            const int kb = ks * 8;
            uint32_t a[2][4], b[2][2];
            #pragma unroll
            for (int mt = 0; mt < 2; mt++) {
                int m = wm * 32 + mt * 16;
                a[mt][0] = FU(sXn[(m + g) * S68 + kb + t4]);
                a[mt][1] = FU(sXn[(m + g + 8) * S68 + kb + t4]);
                a[mt][2] = FU(sXn[(m + g) * S68 + kb + t4 + 4]);
                a[mt][3] = FU(sXn[(m + g + 8) * S68 + kb + t4 + 4]);
            }
            #pragma unroll
            for (int nt = 0; nt < 2; nt++) {
                int nn = wn * 16 + nt * 8;
                b[nt][0] = FU(__ldg(&W1[(nn + g) * 64 + kb + t4]));
                b[nt][1] = FU(__ldg(&W1[(nn + g) * 64 + kb + t4 + 4]));
            }
            #pragma unroll
            for (int mt = 0; mt < 2; mt++)
                #pragma unroll
                for (int nt = 0; nt < 2; nt++)
                    mma_tf32(hacc[mt][nt], a[mt], b[nt]);
        }
        #pragma unroll
        for (int mt = 0; mt < 2; mt++) {
            int s0 = wm * 32 + mt * 16 + g;
            #pragma unroll
            for (int nt = 0; nt < 2; nt++) {
                int i0 = wn * 16 + nt * 8 + 2 * t4;
                sHT[i0 * S68 + s0]           = hacc[mt][nt][0] - sXn[s0 * S68 + i0];
                sHT[(i0 + 1) * S68 + s0]     = hacc[mt][nt][1] - sXn[s0 * S68 + i0 + 1];
                sHT[i0 * S68 + s0 + 8]       = hacc[mt][nt][2] - sXn[(s0 + 8) * S68 + i0];
                sHT[(i0 + 1) * S68 + s0 + 8] = hacc[mt][nt][3] - sXn[(s0 + 8) * S68 + i0 + 1];
            }
        }
    }
    __syncthreads();

    // ---- phase 2: h2 = relu(W2 @ h1) (64x64), store into sXn as [i][k] ----
    {
        const int wm = wid >> 2, wn = wid & 3;
        float hacc[2][2][4] = {};
        #pragma unroll
        for (int ks = 0; ks < 8; ks++) {
            const int kb = ks * 8;
            uint32_t a[2][4], b[2][2];
            #pragma unroll
            for (int mt = 0; mt < 2; mt++) {
                int m = wm * 32 + mt * 16;
                a[mt][0] = FU(__ldg(&W2[(m + g) * 64 + kb + t4]));
                a[mt][1] = FU(__ldg(&W2[(m + g + 8) * 64 + kb + t4]));
                a[mt][2] = FU(__ldg(&W2[(m + g) * 64 + kb + t4 + 4]));
                a[mt][3] = FU(__ldg(&W2[(m + g + 8) * 64 + kb + t4 + 4]));
            }
            #pragma unroll
            for (int nt = 0; nt < 2; nt++) {
                int nn = wn * 16 + nt * 8;
                b[nt][0] = FU(sHT[(nn + g) * S68 + kb + t4]);
                b[nt][1] = FU(sHT[(nn + g) * S68 + kb + t4 + 4]);
            }
            #pragma unroll
            for (int mt = 0; mt < 2; mt++)
                #pragma unroll
                for (int nt = 0; nt < 2; nt++)
                    mma_tf32(hacc[mt][nt], a[mt], b[nt]);
        }
        __syncthreads();   // everyone done reading sXn (xn) before overwrite
        #pragma unroll
        for (int mt = 0; mt < 2; mt++) {
            int i0 = wm * 32 + mt * 16 + g;
            #pragma unroll
            for (int nt = 0; nt < 2; nt++) {
                int k = wn * 16 + nt * 8 + 2 * t4;
                sXn[i0 * S68 + k]           = fmaxf(hacc[mt][nt][0], 0.f);
                sXn[i0 * S68 + k + 1]       = fmaxf(hacc[mt][nt][1], 0.f);
                sXn[(i0 + 8) * S68 + k]     = fmaxf(hacc[mt][nt][2], 0.f);
                sXn[(i0 + 8) * S68 + k + 1] = fmaxf(hacc[mt][nt][3], 0.f);
            }
        }
    }
    __syncthreads();

    // ---- phase 3 (two 128-row bands): M = We @ h2 ; R = M @ G ; s1/s2 ----
    #pragma unroll 1
    for (int bnd = 0; bnd < 2; bnd++) {
        const int rloc = 16 * wid;                // local row base 0..112
        const int c0 = bnd * 128 + rloc;          // global channel base
        float macc[8][4] = {}, racc[8][4] = {};
        #pragma unroll
        for (int ks = 0; ks < 8; ks++) {
            const int kb = ks * 8;
            uint32_t a[4], b[8][2];
            a[0] = FU(__ldg(&We[(c0 + g) * 64 + kb + t4]));
            a[1] = FU(__ldg(&We[(c0 + g + 8) * 64 + kb + t4]));
            a[2] = FU(__ldg(&We[(c0 + g) * 64 + kb + t4 + 4]));
            a[3] = FU(__ldg(&We[(c0 + g + 8) * 64 + kb + t4 + 4]));
            #pragma unroll
            for (int nt = 0; nt < 8; nt++) {
                b[nt][0] = FU(sXn[(kb + t4) * S68 + nt * 8 + g]);
                b[nt][1] = FU(sXn[(kb + t4 + 4) * S68 + nt * 8 + g]);
            }
            #pragma unroll
            for (int nt = 0; nt < 8; nt++)
                mma_tf32(macc[nt], a, b[nt]);
        }
        // store M (global + band smem)
        float* Mg = g_M + (size_t)n * Cc * Sn;
        #pragma unroll
        for (int nt = 0; nt < 8; nt++) {
            int col = nt * 8 + 2 * t4;
            *(float2*)(Mg + (c0 + g) * 64 + col)     = make_float2(macc[nt][0], macc[nt][1]);
            *(float2*)(Mg + (c0 + g + 8) * 64 + col) = make_float2(macc[nt][2], macc[nt][3]);
            sMb[(rloc + g) * S68 + col]     = macc[nt][0];
            sMb[(rloc + g) * S68 + col + 1] = macc[nt][1];
            sMb[(rloc + g + 8) * S68 + col]     = macc[nt][2];
            sMb[(rloc + g + 8) * S68 + col + 1] = macc[nt][3];
        }
        __syncthreads();
        // R = Mb @ G
        #pragma unroll
        for (int ks = 0; ks < 8; ks++) {
            const int kb = ks * 8;
            uint32_t a[4], b[8][2];
            a[0] = FU(sMb[(rloc + g) * S68 + kb + t4]);
            a[1] = FU(sMb[(rloc + g + 8) * S68 + kb + t4]);
            a[2] = FU(sMb[(rloc + g) * S68 + kb + t4 + 4]);
            a[3] = FU(sMb[(rloc + g + 8) * S68 + kb + t4 + 4]);
            #pragma unroll
            for (int nt = 0; nt < 8; nt++) {
                b[nt][0] = FU(sG[(nt * 8 + g) * S68 + kb + t4]);
                b[nt][1] = FU(sG[(nt * 8 + g) * S68 + kb + t4 + 4]);
            }
            #pragma unroll
            for (int nt = 0; nt < 8; nt++)
                mma_tf32(racc[nt], a, b[nt]);
        }
        float s10 = 0.f, s11 = 0.f, s20 = 0.f, s21 = 0.f;
        #pragma unroll
        for (int nt = 0; nt < 8; nt++) {
            s10 += macc[nt][0] + macc[nt][1];
            s11 += macc[nt][2] + macc[nt][3];
            s20 += macc[nt][0] * racc[nt][0] + macc[nt][1] * racc[nt][1];
            s21 += macc[nt][2] * racc[nt][2] + macc[nt][3] * racc[nt][3];
        }
        s10 += __shfl_xor_sync(0xffffffffu, s10, 1); s10 += __shfl_xor_sync(0xffffffffu, s10, 2);
        s11 += __shfl_xor_sync(0xffffffffu, s11, 1); s11 += __shfl_xor_sync(0xffffffffu, s11, 2);
        s20 += __shfl_xor_sync(0xffffffffu, s20, 1); s20 += __shfl_xor_sync(0xffffffffu, s20, 2);
        s21 += __shfl_xor_sync(0xffffffffu, s21, 1); s21 += __shfl_xor_sync(0xffffffffu, s21, 2);
        if (t4 == 0) {
            g_s1[n * Cc + c0 + g] = s10;     g_s2[n * Cc + c0 + g] = s20;
            g_s1[n * Cc + c0 + g + 8] = s11; g_s2[n * Cc + c0 + g + 8] = s21;
        }
        __syncthreads();
    }
}

// ================= k7g: out = x + BN(M(128x64) @ comb-tile(64x128)) ==================
// computes mean/istd for its 128 channels from g_s1/g_s2 in-block (folds old k6r).
__global__ void __launch_bounds__(256) k7g_mma(
    const float* __restrict__ x, const float* __restrict__ gamma,
    const float* __restrict__ beta, float* __restrict__ out)
{
    extern __shared__ float smf[];
    uint32_t* smu = (uint32_t*)smf;
    float* sMean = smf + GEMM_SMEM_FLOATS;        // [128]
    float* sIstd = sMean + 128;                   // [128]
    const int n = blockIdx.z, band = blockIdx.y, tileX = blockIdx.x;
    const int r0 = band * 128, k0 = tileX * NT;
    const int tid = threadIdx.x, wid = tid >> 5, lane = tid & 31;
    const int wm = wid >> 2, wn = wid & 3;
    const int g = lane >> 2, t4 = lane & 3;
    const uint32_t sb = smem_u32(smf);
    float acc[4][4][4] = {};
    const float* Mb = g_M + (size_t)n * Cc * Sn;
    const float* Cb = g_t + (size_t)n * Sn * HWn + k0;

    #pragma unroll
    for (int ch = 0; ch < 2; ch++) {
        const uint32_t base = sb + (ch ? OFF_A1 : OFF_A0) * 4;
        #pragma unroll
        for (int it = 0; it < 4; it++) {
            int idx = tid + it * 256;
            int m = idx >> 3, k4 = idx & 7;
            cp16(base + (uint32_t)(m * SA_STRIDE + k4 * 4) * 4,
                 Mb + (size_t)(r0 + m) * 64 + ch * 32 + k4 * 4);
        }
    }
    CP_COMMIT();
    // BN stats for this channel band (redundant per block; 4 KB of L2-hot reads)
    if (tid < 128) {
        int c = r0 + tid;
        float s = 0.f, q = 0.f;
        #pragma unroll
        for (int nn = 0; nn < Nn; nn++) { s += g_s1[nn * Cc + c]; q += g_s2[nn * Cc + c]; }
        float mean = s / CNT;
        float var = q / CNT - mean * mean;
        sMean[tid] = mean;
        sIstd[tid] = rsqrtf(var + 1e-5f);
    }
    #pragma unroll
    for (int ch = 0; ch < 2; ch++) {
        uint32_t* uB = smu + (ch ? OFF_B1 : OFF_B0);
        #pragma unroll
        for (int it = 0; it < 4; it++) {
            int idx = tid + it * 256;
            int k = idx >> 5, n4 = idx & 31;
            int row = ch * 32 + k;
            float4 v = *(const float4*)(Cb + (size_t)row * HWn + n4 * 4);
            float Mr = __ldg(&g_rM[n * 64 + row]), Ir = __ldg(&g_rI[n * 64 + row]);
            uint4 u = {FU(__expf(v.x - Mr) * Ir), FU(__expf(v.y - Mr) * Ir),
                       FU(__expf(v.z - Mr) * Ir), FU(__expf(v.w - Mr) * Ir)};
            *(uint4*)&uB[k * SB_STRIDE + n4 * 4] = u;
        }
    }
    CP_WAIT0();
    __syncthreads();

    #pragma unroll
    for (int ch = 0; ch < 2; ch++) {
        const float* fA = smf + (ch ? OFF_A1 : OFF_A0);
        const uint32_t* uB = smu + (ch ? OFF_B1 : OFF_B0);
        #pragma unroll
        for (int ks = 0; ks < 4; ks++) {
            const int kb = ks * 8;
            uint32_t a[4][4], b[4][2];
            #pragma unroll
            for (int mt = 0; mt < 4; mt++) {
                int m = wm * 64 + mt * 16;
                a[mt][0] = FU(fA[(m + g) * SA_STRIDE + kb + t4]);
                a[mt][1] = FU(fA[(m + g + 8) * SA_STRIDE + kb + t4]);
                a[mt][2] = FU(fA[(m + g) * SA_STRIDE + kb + t4 + 4]);
                a[mt][3] = FU(fA[(m + g + 8) * SA_STRIDE + kb + t4 + 4]);
            }
            #pragma unroll
            for (int nt = 0; nt < 4; nt++) {
                int nn = wn * 32 + nt * 8;
                b[nt][0] = uB[(kb + t4) * SB_STRIDE + nn + g];
                b[nt][1] = uB[(kb + t4 + 4) * SB_STRIDE + nn + g];
            }
            #pragma unroll
            for (int mt = 0; mt < 4; mt++)
                #pragma unroll
                for (int nt = 0; nt < 4; nt++)
                    mma_tf32(acc[mt][nt], a[mt], b[nt]);
        }
    }

    const int nbase = k0 + wn * 32 + 2 * t4;
    #pragma unroll
    for (int mt = 0; mt < 4; mt++) {
        int lA = wm * 64 + mt * 16 + g;
        int cA = r0 + lA, cB = cA + 8;
        float gA = gamma[cA] * sIstd[lA],     bA = beta[cA] - sMean[lA] * gA;
        float gB = gamma[cB] * sIstd[lA + 8], bB = beta[cB] - sMean[lA + 8] * gB;
        const float* x0p = x + (size_t)(n * Cc + cA) * HWn;
        const float* x1p = x0p + (size_t)8 * HWn;
        float* o0p = out + (size_t)(n * Cc + cA) * HWn;
        float* o1p = o0p + (size_t)8 * HWn;
        #pragma unroll
        for (int nt = 0; nt < 4; nt++) {
            int col = nbase + nt * 8;
            float2 xv0 = *(const float2*)(x0p + col);
            float2 xv1 = *(const float2*)(x1p + col);
            *(float2*)(o0p + col) = make_float2(xv0.x + acc[mt][nt][0] * gA + bA,
                                                xv0.y + acc[mt][nt][1] * gA + bA);
            *(float2*)(o1p + col) = make_float2(xv1.x + acc[mt][nt][2] * gB + bB,
                                                xv1.y + acc[mt][nt][3] * gB + bB);
        }
    }
}

// ---------------- launch ----------------
extern "C" void kernel_launch(void* const* d_in, const int* in_sizes, int n_in,
                              void* d_out, int out_size)
{
    const float* x     = (const float*)d_in[0];
    const float* edge  = (const float*)d_in[1];
    const float* Ws    = (const float*)d_in[2];
    const float* bs    = (const float*)d_in[3];
    const float* Wp    = (const float*)d_in[4];
    const float* bp    = (const float*)d_in[5];
    const float* W1    = (const float*)d_in[6];
    const float* W2    = (const float*)d_in[7];
    const float* We    = (const float*)d_in[8];
    const float* gamma = (const float*)d_in[9];
    const float* beta  = (const float*)d_in[10];
    float* out = (float*)d_out;

    cudaFuncSetAttribute(k1_mma, cudaFuncAttributeMaxDynamicSharedMemorySize, K1_SMEM_BYTES);
    cudaFuncSetAttribute(k4f,    cudaFuncAttributeMaxDynamicSharedMemorySize, K4F_SMEM);
    cudaFuncSetAttribute(k7g_mma, cudaFuncAttributeMaxDynamicSharedMemorySize, K7_SMEM_BYTES);

    k1_mma <<<dim3(NTILE, Nn), 256, K1_SMEM_BYTES>>>(x, edge, Ws, bs, Wp, bp);
    k3g_mma<<<dim3(SPLIT, Nn), 256>>>();
    k4f    <<<Nn, 256, K4F_SMEM>>>(W1, W2, We);
    k7g_mma<<<dim3(NTILE, 2, Nn), 256, K7_SMEM_BYTES>>>(x, gamma, beta, out);
}